// round 1
// baseline (speedup 1.0000x reference)
#include <cuda_runtime.h>
#include <cuda_bf16.h>
#include <cstdint>

// Problem constants
#define SLEN   2048
#define BSZ    8
#define IN_DIM 1024
#define NH     16
#define DH     64
#define NROWS  (SLEN*BSZ)              // 16384
#define NOUT   (NH*(3*DH+1))           // 3088

// ---------------- device scratch (no cudaMalloc allowed) ----------------
__device__ float g_h[(size_t)NROWS * IN_DIM];      // 64MB   LN output
__device__ float g_qkvb[(size_t)NROWS * NOUT];     // 202MB  GEMM1 output
__device__ float g_q[(size_t)BSZ*NH*SLEN*DH];      // 64MB   [bh][t][d]
__device__ float g_k[(size_t)BSZ*NH*SLEN*DH];      // 64MB
__device__ float g_v[(size_t)BSZ*NH*SLEN*DH];      // 64MB
__device__ float g_beta[(size_t)BSZ*NH*SLEN];      // 1MB
__device__ float g_o[(size_t)NROWS * IN_DIM];      // 64MB   scan output [t][b][h*64+d]

// ---------------- helpers ----------------
__device__ __forceinline__ void cp_async16(void* smem_dst, const void* gsrc) {
    unsigned s = (unsigned)__cvta_generic_to_shared(smem_dst);
    asm volatile("cp.async.cg.shared.global [%0], [%1], 16;\n" :: "r"(s), "l"(gsrc));
}
__device__ __forceinline__ void cp_async4(void* smem_dst, const void* gsrc) {
    unsigned s = (unsigned)__cvta_generic_to_shared(smem_dst);
    asm volatile("cp.async.ca.shared.global [%0], [%1], 4;\n" :: "r"(s), "l"(gsrc));
}
__device__ __forceinline__ float elu_p1(float x) {
    return x > 0.f ? x + 1.f : __expf(x);
}

// ---------------- LayerNorm: one block per row of 1024 ----------------
__global__ __launch_bounds__(256) void ln_kernel(
    const float* __restrict__ x, const float* __restrict__ w,
    const float* __restrict__ b, float* __restrict__ h)
{
    int row = blockIdx.x;
    int t = threadIdx.x;
    const float4* xr = (const float4*)(x + (size_t)row * IN_DIM);
    float4 v = xr[t];
    float s  = v.x + v.y + v.z + v.w;
    float ss = v.x*v.x + v.y*v.y + v.z*v.z + v.w*v.w;
    #pragma unroll
    for (int o = 16; o; o >>= 1) {
        s  += __shfl_xor_sync(0xffffffffu, s,  o);
        ss += __shfl_xor_sync(0xffffffffu, ss, o);
    }
    __shared__ float rs[8], rss[8];
    if ((t & 31) == 0) { rs[t >> 5] = s; rss[t >> 5] = ss; }
    __syncthreads();
    float S = 0.f, SS = 0.f;
    #pragma unroll
    for (int i = 0; i < 8; i++) { S += rs[i]; SS += rss[i]; }
    float mu = S * (1.f / IN_DIM);
    float var = SS * (1.f / IN_DIM) - mu * mu;
    float rstd = rsqrtf(var + 1e-5f);
    float4 wv = ((const float4*)w)[t];
    float4 bv = ((const float4*)b)[t];
    float4 o;
    o.x = (v.x - mu) * rstd * wv.x + bv.x;
    o.y = (v.y - mu) * rstd * wv.y + bv.y;
    o.z = (v.z - mu) * rstd * wv.z + bv.z;
    o.w = (v.w - mu) * rstd * wv.w + bv.w;
    ((float4*)(h + (size_t)row * IN_DIM))[t] = o;
}

// ---------------- tiled SGEMM: C = A[MxK] * B[KxN] (+Res), 128x128x16 ----------------
__global__ __launch_bounds__(256) void sgemm128(
    const float* __restrict__ A, const float* __restrict__ B,
    const float* __restrict__ Res, float* __restrict__ C,
    int M, int N, int K)
{
    __shared__ float As[16][128];
    __shared__ float Bs[16][132];
    const int tid = threadIdx.x;
    const int bx = blockIdx.x, by = blockIdx.y;
    const int tx = tid & 15;
    const int ty = tid >> 4;
    const int row0 = by * 128;
    const int col0 = bx * 128;

    float acc[8][8];
    #pragma unroll
    for (int i = 0; i < 8; i++)
        #pragma unroll
        for (int j = 0; j < 8; j++) acc[i][j] = 0.f;

    for (int k0 = 0; k0 < K; k0 += 16) {
        #pragma unroll
        for (int it = 0; it < 2; it++) {
            int idx4 = tid + it * 256;
            int r  = idx4 >> 2;
            int c4 = idx4 & 3;
            float4 v = *(const float4*)&A[(size_t)(row0 + r) * K + k0 + c4 * 4];
            As[c4*4+0][r] = v.x; As[c4*4+1][r] = v.y;
            As[c4*4+2][r] = v.z; As[c4*4+3][r] = v.w;
        }
        #pragma unroll
        for (int it = 0; it < 2; it++) {
            int idx4 = tid + it * 256;
            int r  = idx4 >> 5;
            int c4 = idx4 & 31;
            int col = col0 + c4 * 4;
            float4 v = make_float4(0.f, 0.f, 0.f, 0.f);
            if (col < N) v = *(const float4*)&B[(size_t)(k0 + r) * N + col];
            Bs[r][c4*4+0] = v.x; Bs[r][c4*4+1] = v.y;
            Bs[r][c4*4+2] = v.z; Bs[r][c4*4+3] = v.w;
        }
        __syncthreads();
        #pragma unroll
        for (int kk = 0; kk < 16; kk++) {
            float a[8], bf[8];
            #pragma unroll
            for (int i = 0; i < 8; i++) a[i] = As[kk][ty*8 + i];
            #pragma unroll
            for (int j = 0; j < 8; j++) bf[j] = Bs[kk][tx*8 + j];
            #pragma unroll
            for (int i = 0; i < 8; i++)
                #pragma unroll
                for (int j = 0; j < 8; j++)
                    acc[i][j] = fmaf(a[i], bf[j], acc[i][j]);
        }
        __syncthreads();
    }
    #pragma unroll
    for (int i = 0; i < 8; i++) {
        int row = row0 + ty*8 + i;
        if (Res) {
            #pragma unroll
            for (int j = 0; j < 8; j++) {
                int col = col0 + tx*8 + j;
                if (col < N) {
                    size_t off = (size_t)row * N + col;
                    C[off] = acc[i][j] + Res[off];
                }
            }
        } else {
            #pragma unroll
            for (int j = 0; j < 8; j++) {
                int col = col0 + tx*8 + j;
                if (col < N) C[(size_t)row * N + col] = acc[i][j];
            }
        }
    }
}

// ---------------- transform: elu_p1+sum_norm on q,k; sigmoid beta; relayout ----------------
// one warp per (t,b,h)
__global__ __launch_bounds__(256) void transform_kernel(
    const float* __restrict__ qkvb,
    float* __restrict__ Q, float* __restrict__ Kk,
    float* __restrict__ V, float* __restrict__ Beta)
{
    int gw   = blockIdx.x * 8 + (threadIdx.x >> 5);
    int lane = threadIdx.x & 31;
    int h  = gw & 15;
    int tb = gw >> 4;            // t*BSZ + b
    int b  = tb & 7;
    int t  = tb >> 3;
    const float* src = qkvb + (size_t)tb * NOUT + h * (3*DH + 1);
    size_t dst = ((size_t)(b * NH + h) * SLEN + t) * DH;

    // q
    float q0 = elu_p1(src[lane]);
    float q1 = elu_p1(src[lane + 32]);
    float s = q0 + q1;
    #pragma unroll
    for (int o = 16; o; o >>= 1) s += __shfl_xor_sync(0xffffffffu, s, o);
    float inv = 1.f / s;
    Q[dst + lane]      = q0 * inv;
    Q[dst + lane + 32] = q1 * inv;
    // k
    float k0 = elu_p1(src[64 + lane]);
    float k1 = elu_p1(src[96 + lane]);
    s = k0 + k1;
    #pragma unroll
    for (int o = 16; o; o >>= 1) s += __shfl_xor_sync(0xffffffffu, s, o);
    inv = 1.f / s;
    Kk[dst + lane]      = k0 * inv;
    Kk[dst + lane + 32] = k1 * inv;
    // v
    V[dst + lane]      = src[128 + lane];
    V[dst + lane + 32] = src[160 + lane];
    // beta
    if (lane == 0) {
        float x = src[192];
        Beta[(size_t)(b * NH + h) * SLEN + t] = 1.f / (1.f + __expf(-x));
    }
}

// ---------------- delta-rule scan: one block per (b,h) head ----------------
// 256 threads: thread (i,g): row i = tid>>2 (0..63), column group g = tid&3 (16 cols each)
// W row-slice lives in 16 registers per thread. cp.async 4-stage ring for k/v/q/beta.
__global__ __launch_bounds__(256) void scan_kernel(
    const float* __restrict__ Q, const float* __restrict__ Kk,
    const float* __restrict__ V, const float* __restrict__ Beta,
    float* __restrict__ O)
{
    __shared__ __align__(16) float ring[4][196];  // [k 0:64 | v 64:128 | q 128:192 | beta 192]
    const int bh = blockIdx.x;        // 0..127
    const int b = bh >> 4, h = bh & 15;
    const float* Kp = Kk   + (size_t)bh * SLEN * DH;
    const float* Vp = V    + (size_t)bh * SLEN * DH;
    const float* Qp = Q    + (size_t)bh * SLEN * DH;
    const float* Bp = Beta + (size_t)bh * SLEN;
    const int tid = threadIdx.x;
    const int i = tid >> 2;
    const int g = tid & 3;

    float W[16];
    #pragma unroll
    for (int m = 0; m < 16; m++) W[m] = 0.f;

    auto issue = [&](int t) {
        float* stg = ring[t & 3];
        if (tid < 48) {
            int sec = tid >> 4;          // 0=k 1=v 2=q
            int f4  = tid & 15;
            const float* base = (sec == 0) ? Kp : (sec == 1) ? Vp : Qp;
            cp_async16(&stg[sec*64 + f4*4], base + (size_t)t * DH + f4 * 4);
        } else if (tid == 48) {
            cp_async4(&stg[192], Bp + t);
        }
        asm volatile("cp.async.commit_group;\n" ::);
    };

    issue(0); issue(1); issue(2);

    const size_t obase = (size_t)b * IN_DIM + h * DH + i;   // + t*8192

    for (int t = 0; t < SLEN; t++) {
        asm volatile("cp.async.wait_group 2;\n" ::);
        __syncthreads();

        // prefetch next stage (overwrites stage (t-1)&3, fully consumed by now)
        if (t + 3 < SLEN) issue(t + 3);
        else asm volatile("cp.async.commit_group;\n" ::);

        const float* st = ring[t & 3];
        float kv[16], qv[16];
        #pragma unroll
        for (int m = 0; m < 4; m++) {
            float4 k4 = *(const float4*)&st[g*16 + m*4];
            kv[m*4+0] = k4.x; kv[m*4+1] = k4.y; kv[m*4+2] = k4.z; kv[m*4+3] = k4.w;
            float4 q4 = *(const float4*)&st[128 + g*16 + m*4];
            qv[m*4+0] = q4.x; qv[m*4+1] = q4.y; qv[m*4+2] = q4.z; qv[m*4+3] = q4.w;
        }
        float vi   = st[64 + i];
        float beta = st[192];

        // v_old[i] = sum_j W[i,j] k[j]
        float pk0 = 0.f, pk1 = 0.f;
        #pragma unroll
        for (int m = 0; m < 8; m++) {
            pk0 = fmaf(W[m],     kv[m],     pk0);
            pk1 = fmaf(W[m + 8], kv[m + 8], pk1);
        }
        float pk = pk0 + pk1;
        pk += __shfl_xor_sync(0xffffffffu, pk, 1);
        pk += __shfl_xor_sync(0xffffffffu, pk, 2);

        float delta = beta * (vi - pk);

        // W update + out = W_new q
        float po0 = 0.f, po1 = 0.f;
        #pragma unroll
        for (int m = 0; m < 8; m++) {
            W[m]     = fmaf(delta, kv[m],     W[m]);
            po0      = fmaf(W[m],  qv[m],     po0);
            W[m + 8] = fmaf(delta, kv[m + 8], W[m + 8]);
            po1      = fmaf(W[m + 8], qv[m + 8], po1);
        }
        float po = po0 + po1;
        po += __shfl_xor_sync(0xffffffffu, po, 1);
        po += __shfl_xor_sync(0xffffffffu, po, 2);

        if (g == 0) O[(size_t)t * (BSZ * IN_DIM) + obase] = po;
    }
}

// ---------------- launcher ----------------
extern "C" void kernel_launch(void* const* d_in, const int* in_sizes, int n_in,
                              void* d_out, int out_size)
{
    const float* x      = (const float*)d_in[0];
    const float* ln_w   = (const float*)d_in[1];
    const float* ln_b   = (const float*)d_in[2];
    const float* w_slow = (const float*)d_in[3];
    const float* w_out  = (const float*)d_in[4];
    float* out = (float*)d_out;

    float *p_h, *p_qkvb, *p_q, *p_k, *p_v, *p_beta, *p_o;
    cudaGetSymbolAddress((void**)&p_h,    g_h);
    cudaGetSymbolAddress((void**)&p_qkvb, g_qkvb);
    cudaGetSymbolAddress((void**)&p_q,    g_q);
    cudaGetSymbolAddress((void**)&p_k,    g_k);
    cudaGetSymbolAddress((void**)&p_v,    g_v);
    cudaGetSymbolAddress((void**)&p_beta, g_beta);
    cudaGetSymbolAddress((void**)&p_o,    g_o);

    // 1. LayerNorm
    ln_kernel<<<NROWS, 256>>>(x, ln_w, ln_b, p_h);

    // 2. qkvb = h @ w_slow   [16384 x 3088]
    {
        dim3 grid((NOUT + 127) / 128, NROWS / 128);
        sgemm128<<<grid, 256>>>(p_h, w_slow, nullptr, p_qkvb, NROWS, NOUT, IN_DIM);
    }

    // 3. transform -> q,k,v,beta in [bh][t][d] layout
    transform_kernel<<<(NROWS * NH) / 8, 256>>>(p_qkvb, p_q, p_k, p_v, p_beta);

    // 4. delta-rule scan
    scan_kernel<<<BSZ * NH, 256>>>(p_q, p_k, p_v, p_beta, p_o);

    // 5. out = x + scan_out @ w_out   [16384 x 1024]
    {
        dim3 grid(IN_DIM / 128, NROWS / 128);
        sgemm128<<<grid, 256>>>(p_o, w_out, x, out, NROWS, IN_DIM, IN_DIM);
    }
}

// round 3
// speedup vs baseline: 1.2468x; 1.2468x over previous
#include <cuda_runtime.h>
#include <cuda_bf16.h>
#include <cstdint>

// Problem constants
#define SLEN   2048
#define BSZ    8
#define IN_DIM 1024
#define NH     16
#define DH     64
#define NROWS  (SLEN*BSZ)              // 16384
#define NOUT   (NH*(3*DH+1))           // 3088

// ---------------- device scratch (no cudaMalloc allowed) ----------------
__device__ float g_h[(size_t)NROWS * IN_DIM];      // 64MB   LN output
__device__ float g_qkvb[(size_t)NROWS * NOUT];     // 202MB  GEMM1 output
__device__ float g_q[(size_t)BSZ*NH*SLEN*DH];      // 64MB   [bh][t][d]
__device__ float g_k[(size_t)BSZ*NH*SLEN*DH];      // 64MB
__device__ float g_v[(size_t)BSZ*NH*SLEN*DH];      // 64MB
__device__ float g_beta[(size_t)BSZ*NH*SLEN];      // 1MB
__device__ float g_o[(size_t)NROWS * IN_DIM];      // 64MB   scan output [t][b][h*64+d]

// ---------------- helpers ----------------
__device__ __forceinline__ void cp_async16(void* smem_dst, const void* gsrc) {
    unsigned s = (unsigned)__cvta_generic_to_shared(smem_dst);
    asm volatile("cp.async.cg.shared.global [%0], [%1], 16;\n" :: "r"(s), "l"(gsrc));
}
__device__ __forceinline__ void cp_async4(void* smem_dst, const void* gsrc) {
    unsigned s = (unsigned)__cvta_generic_to_shared(smem_dst);
    asm volatile("cp.async.ca.shared.global [%0], [%1], 4;\n" :: "r"(s), "l"(gsrc));
}
__device__ __forceinline__ float elu_p1(float x) {
    return x > 0.f ? x + 1.f : __expf(x);
}
// split f32 into tf32 hi + tf32 lo (3xTF32 compensation)
__device__ __forceinline__ void split_tf32(float x, uint32_t& hi, uint32_t& lo) {
    asm("cvt.rna.tf32.f32 %0, %1;" : "=r"(hi) : "f"(x));
    float r = x - __uint_as_float(hi);
    asm("cvt.rna.tf32.f32 %0, %1;" : "=r"(lo) : "f"(r));
}
__device__ __forceinline__ void mma_tf32(float* d, const uint32_t* a, const uint32_t* b) {
    asm volatile("mma.sync.aligned.m16n8k8.row.col.f32.tf32.tf32.f32 "
        "{%0,%1,%2,%3}, {%4,%5,%6,%7}, {%8,%9}, {%0,%1,%2,%3};"
        : "+f"(d[0]), "+f"(d[1]), "+f"(d[2]), "+f"(d[3])
        : "r"(a[0]), "r"(a[1]), "r"(a[2]), "r"(a[3]), "r"(b[0]), "r"(b[1]));
}

// ---------------- LayerNorm: one block per row of 1024 ----------------
__global__ __launch_bounds__(256) void ln_kernel(
    const float* __restrict__ x, const float* __restrict__ w,
    const float* __restrict__ b, float* __restrict__ h)
{
    int row = blockIdx.x;
    int t = threadIdx.x;
    const float4* xr = (const float4*)(x + (size_t)row * IN_DIM);
    float4 v = xr[t];
    float s  = v.x + v.y + v.z + v.w;
    float ss = v.x*v.x + v.y*v.y + v.z*v.z + v.w*v.w;
    #pragma unroll
    for (int o = 16; o; o >>= 1) {
        s  += __shfl_xor_sync(0xffffffffu, s,  o);
        ss += __shfl_xor_sync(0xffffffffu, ss, o);
    }
    __shared__ float rs[8], rss[8];
    if ((t & 31) == 0) { rs[t >> 5] = s; rss[t >> 5] = ss; }
    __syncthreads();
    float S = 0.f, SS = 0.f;
    #pragma unroll
    for (int i = 0; i < 8; i++) { S += rs[i]; SS += rss[i]; }
    float mu = S * (1.f / IN_DIM);
    float var = SS * (1.f / IN_DIM) - mu * mu;
    float rstd = rsqrtf(var + 1e-5f);
    float4 wv = ((const float4*)w)[t];
    float4 bv = ((const float4*)b)[t];
    float4 o;
    o.x = (v.x - mu) * rstd * wv.x + bv.x;
    o.y = (v.y - mu) * rstd * wv.y + bv.y;
    o.z = (v.z - mu) * rstd * wv.z + bv.z;
    o.w = (v.w - mu) * rstd * wv.w + bv.w;
    ((float4*)(h + (size_t)row * IN_DIM))[t] = o;
}

// ---------------- 3xTF32 tensor-core GEMM: C = A[MxK] @ B[KxN] (+Res) ----------------
// BM=128, BN=128, BK=16, 256 threads = 8 warps (2x4), warp tile 64x32.
#define GBM 128
#define GBN 128
#define GBK 16
#define AS_STRIDE 20
#define BS_STRIDE 136

__global__ __launch_bounds__(256, 1) void gemm_tf32(
    const float* __restrict__ A, const float* __restrict__ B,
    const float* __restrict__ Res, float* __restrict__ C,
    int M, int N, int K)
{
    __shared__ float As[2][GBM * AS_STRIDE];
    __shared__ float Bs[2][GBK * BS_STRIDE];

    const int tid  = threadIdx.x;
    const int warp = tid >> 5;
    const int lane = tid & 31;
    const int gid  = lane >> 2;   // 0..7
    const int tig  = lane & 3;    // 0..3
    const int wm   = warp & 1;    // warp row (0..1), 64 rows each
    const int wn   = warp >> 1;   // warp col (0..3), 32 cols each
    const int row0 = blockIdx.y * GBM;
    const int col0 = blockIdx.x * GBN;

    float acc[4][4][4];
    #pragma unroll
    for (int i = 0; i < 4; i++)
        #pragma unroll
        for (int j = 0; j < 4; j++)
            #pragma unroll
            for (int k = 0; k < 4; k++) acc[i][j][k] = 0.f;

    const int nk = K / GBK;

    auto load_tile = [&](int kt, int buf) {
        int k0 = kt * GBK;
        #pragma unroll
        for (int it = 0; it < 2; it++) {
            int idx = tid + it * 256;
            int m  = idx >> 2;
            int c4 = idx & 3;
            cp_async16(&As[buf][m * AS_STRIDE + c4 * 4],
                       &A[(size_t)(row0 + m) * K + k0 + c4 * 4]);
        }
        #pragma unroll
        for (int it = 0; it < 2; it++) {
            int idx = tid + it * 256;
            int k  = idx >> 5;
            int n4 = idx & 31;
            int col = col0 + n4 * 4;
            if (col < N)
                cp_async16(&Bs[buf][k * BS_STRIDE + n4 * 4],
                           &B[(size_t)(k0 + k) * N + col]);
        }
        asm volatile("cp.async.commit_group;\n" ::);
    };

    load_tile(0, 0);

    for (int kt = 0; kt < nk; kt++) {
        int buf = kt & 1;
        if (kt + 1 < nk) load_tile(kt + 1, buf ^ 1);
        else asm volatile("cp.async.commit_group;\n" ::);
        asm volatile("cp.async.wait_group 1;\n" ::);
        __syncthreads();

        #pragma unroll
        for (int kh = 0; kh < 2; kh++) {
            const int kb = kh * 8;
            uint32_t Ahi[4][4], Alo[4][4];
            #pragma unroll
            for (int mt = 0; mt < 4; mt++) {
                int mrow = wm * 64 + mt * 16 + gid;
                float x0 = As[buf][(mrow    ) * AS_STRIDE + kb + tig    ];
                float x1 = As[buf][(mrow + 8) * AS_STRIDE + kb + tig    ];
                float x2 = As[buf][(mrow    ) * AS_STRIDE + kb + tig + 4];
                float x3 = As[buf][(mrow + 8) * AS_STRIDE + kb + tig + 4];
                split_tf32(x0, Ahi[mt][0], Alo[mt][0]);
                split_tf32(x1, Ahi[mt][1], Alo[mt][1]);
                split_tf32(x2, Ahi[mt][2], Alo[mt][2]);
                split_tf32(x3, Ahi[mt][3], Alo[mt][3]);
            }
            uint32_t Bhi[4][2], Blo[4][2];
            #pragma unroll
            for (int nt = 0; nt < 4; nt++) {
                int ncol = wn * 32 + nt * 8 + gid;
                float y0 = Bs[buf][(kb + tig    ) * BS_STRIDE + ncol];
                float y1 = Bs[buf][(kb + tig + 4) * BS_STRIDE + ncol];
                split_tf32(y0, Bhi[nt][0], Blo[nt][0]);
                split_tf32(y1, Bhi[nt][1], Blo[nt][1]);
            }
            #pragma unroll
            for (int mt = 0; mt < 4; mt++)
                #pragma unroll
                for (int nt = 0; nt < 4; nt++) {
                    mma_tf32(acc[mt][nt], Alo[mt], Bhi[nt]);
                    mma_tf32(acc[mt][nt], Ahi[mt], Blo[nt]);
                    mma_tf32(acc[mt][nt], Ahi[mt], Bhi[nt]);
                }
        }
        __syncthreads();
    }

    #pragma unroll
    for (int mt = 0; mt < 4; mt++) {
        #pragma unroll
        for (int nt = 0; nt < 4; nt++) {
            int r = row0 + wm * 64 + mt * 16 + gid;
            int c = col0 + wn * 32 + nt * 8 + 2 * tig;
            if (c < N) {
                size_t o0 = (size_t)r * N + c;
                size_t o1 = (size_t)(r + 8) * N + c;
                float2 v0 = make_float2(acc[mt][nt][0], acc[mt][nt][1]);
                float2 v1 = make_float2(acc[mt][nt][2], acc[mt][nt][3]);
                if (Res) {
                    float2 r0 = *(const float2*)&Res[o0];
                    float2 r1 = *(const float2*)&Res[o1];
                    v0.x += r0.x; v0.y += r0.y;
                    v1.x += r1.x; v1.y += r1.y;
                }
                *(float2*)&C[o0] = v0;
                *(float2*)&C[o1] = v1;
            }
        }
    }
}

// ---------------- transform: elu_p1+sum_norm on q,k; sigmoid beta; relayout ----------------
__global__ __launch_bounds__(256) void transform_kernel(
    const float* __restrict__ qkvb,
    float* __restrict__ Q, float* __restrict__ Kk,
    float* __restrict__ V, float* __restrict__ Beta)
{
    int gw   = blockIdx.x * 8 + (threadIdx.x >> 5);
    int lane = threadIdx.x & 31;
    int h  = gw & 15;
    int tb = gw >> 4;            // t*BSZ + b
    int b  = tb & 7;
    int t  = tb >> 3;
    const float* src = qkvb + (size_t)tb * NOUT + h * (3*DH + 1);
    size_t dst = ((size_t)(b * NH + h) * SLEN + t) * DH;

    float q0 = elu_p1(src[lane]);
    float q1 = elu_p1(src[lane + 32]);
    float s = q0 + q1;
    #pragma unroll
    for (int o = 16; o; o >>= 1) s += __shfl_xor_sync(0xffffffffu, s, o);
    float inv = 1.f / s;
    Q[dst + lane]      = q0 * inv;
    Q[dst + lane + 32] = q1 * inv;

    float k0 = elu_p1(src[64 + lane]);
    float k1 = elu_p1(src[96 + lane]);
    s = k0 + k1;
    #pragma unroll
    for (int o = 16; o; o >>= 1) s += __shfl_xor_sync(0xffffffffu, s, o);
    inv = 1.f / s;
    Kk[dst + lane]      = k0 * inv;
    Kk[dst + lane + 32] = k1 * inv;

    V[dst + lane]      = src[128 + lane];
    V[dst + lane + 32] = src[160 + lane];

    if (lane == 0) {
        float x = src[192];
        Beta[(size_t)(b * NH + h) * SLEN + t] = 1.f / (1.f + __expf(-x));
    }
}

// ---------------- delta-rule scan: one WARP per (head, 8-row octet) ----------------
// grid = 1024 blocks x 32 threads. No block barriers; per-warp cp.async ring.
// lane (rloc,g): row i = w*8 + (lane>>2), column group g = lane&3 (16 cols each).
__global__ __launch_bounds__(32) void scan_kernel(
    const float* __restrict__ Q, const float* __restrict__ Kk,
    const float* __restrict__ V, const float* __restrict__ Beta,
    float* __restrict__ O)
{
    __shared__ __align__(16) float ring[4][144]; // [k 0:64 | q 64:128 | v8 128:136 | beta 136]
    const int bh = blockIdx.x >> 3;   // 0..127
    const int w  = blockIdx.x & 7;    // row octet 0..7
    const int b = bh >> 4, h = bh & 15;
    const float* Kp = Kk   + (size_t)bh * SLEN * DH;
    const float* Vp = V    + (size_t)bh * SLEN * DH;
    const float* Qp = Q    + (size_t)bh * SLEN * DH;
    const float* Bp = Beta + (size_t)bh * SLEN;
    const int lane = threadIdx.x;
    const int rloc = lane >> 2;       // 0..7
    const int i = w * 8 + rloc;       // global row 0..63
    const int g = lane & 3;

    float W[16];
    #pragma unroll
    for (int m = 0; m < 16; m++) W[m] = 0.f;

    auto issue = [&](int t) {
        float* stg = ring[t & 3];
        if (lane < 16) cp_async16(stg + lane * 4, Kp + (size_t)t * DH + lane * 4);
        else           cp_async16(stg + 64 + (lane - 16) * 4, Qp + (size_t)t * DH + (lane - 16) * 4);
        if (lane == 0) {
            cp_async16(stg + 128, Vp + (size_t)t * DH + w * 8);
            cp_async16(stg + 132, Vp + (size_t)t * DH + w * 8 + 4);
        }
        if (lane == 1) cp_async4(stg + 136, Bp + t);
        asm volatile("cp.async.commit_group;\n" ::);
    };

    issue(0); issue(1); issue(2);

    const size_t obase = (size_t)b * IN_DIM + h * DH + i;

    for (int t = 0; t < SLEN; t++) {
        asm volatile("cp.async.wait_group 2;\n" ::);
        __syncwarp();

        const float* st = ring[t & 3];
        float kv[16], qv[16];
        #pragma unroll
        for (int m = 0; m < 4; m++) {
            float4 k4 = *(const float4*)&st[g * 16 + m * 4];
            kv[m*4+0] = k4.x; kv[m*4+1] = k4.y; kv[m*4+2] = k4.z; kv[m*4+3] = k4.w;
            float4 q4 = *(const float4*)&st[64 + g * 16 + m * 4];
            qv[m*4+0] = q4.x; qv[m*4+1] = q4.y; qv[m*4+2] = q4.z; qv[m*4+3] = q4.w;
        }
        float vi   = st[128 + rloc];
        float beta = st[136];

        if (t + 3 < SLEN) issue(t + 3);
        else asm volatile("cp.async.commit_group;\n" ::);

        // v_old[i] = sum_j W[i,j] k[j]  (partial over 16 cols, reduce over 4 lanes)
        float pk0 = 0.f, pk1 = 0.f;
        #pragma unroll
        for (int m = 0; m < 8; m++) {
            pk0 = fmaf(W[m],     kv[m],     pk0);
            pk1 = fmaf(W[m + 8], kv[m + 8], pk1);
        }
        float pk = pk0 + pk1;
        pk += __shfl_xor_sync(0xffffffffu, pk, 1);
        pk += __shfl_xor_sync(0xffffffffu, pk, 2);

        float delta = beta * (vi - pk);

        float po0 = 0.f, po1 = 0.f;
        #pragma unroll
        for (int m = 0; m < 8; m++) {
            W[m]     = fmaf(delta, kv[m],     W[m]);
            po0      = fmaf(W[m],  qv[m],     po0);
            W[m + 8] = fmaf(delta, kv[m + 8], W[m + 8]);
            po1      = fmaf(W[m + 8], qv[m + 8], po1);
        }
        float po = po0 + po1;
        po += __shfl_xor_sync(0xffffffffu, po, 1);
        po += __shfl_xor_sync(0xffffffffu, po, 2);

        if (g == 0) O[(size_t)t * (BSZ * IN_DIM) + obase] = po;
    }
}

// ---------------- launcher ----------------
extern "C" void kernel_launch(void* const* d_in, const int* in_sizes, int n_in,
                              void* d_out, int out_size)
{
    const float* x      = (const float*)d_in[0];
    const float* ln_w   = (const float*)d_in[1];
    const float* ln_b   = (const float*)d_in[2];
    const float* w_slow = (const float*)d_in[3];
    const float* w_out  = (const float*)d_in[4];
    float* out = (float*)d_out;

    float *p_h, *p_qkvb, *p_q, *p_k, *p_v, *p_beta, *p_o;
    cudaGetSymbolAddress((void**)&p_h,    g_h);
    cudaGetSymbolAddress((void**)&p_qkvb, g_qkvb);
    cudaGetSymbolAddress((void**)&p_q,    g_q);
    cudaGetSymbolAddress((void**)&p_k,    g_k);
    cudaGetSymbolAddress((void**)&p_v,    g_v);
    cudaGetSymbolAddress((void**)&p_beta, g_beta);
    cudaGetSymbolAddress((void**)&p_o,    g_o);

    // 1. LayerNorm
    ln_kernel<<<NROWS, 256>>>(x, ln_w, ln_b, p_h);

    // 2. qkvb = h @ w_slow   [16384 x 3088]  (3xTF32 tensor cores)
    {
        dim3 grid((NOUT + GBN - 1) / GBN, NROWS / GBM);
        gemm_tf32<<<grid, 256>>>(p_h, w_slow, nullptr, p_qkvb, NROWS, NOUT, IN_DIM);
    }

    // 3. transform -> q,k,v,beta in [bh][t][d] layout
    transform_kernel<<<(NROWS * NH) / 8, 256>>>(p_qkvb, p_q, p_k, p_v, p_beta);

    // 4. delta-rule scan (one warp per head-octet)
    scan_kernel<<<BSZ * NH * 8, 32>>>(p_q, p_k, p_v, p_beta, p_o);

    // 5. out = x + scan_out @ w_out   [16384 x 1024]  (3xTF32 tensor cores)
    {
        dim3 grid(IN_DIM / GBN, NROWS / GBM);
        gemm_tf32<<<grid, 256>>>(p_o, w_out, x, out, NROWS, IN_DIM, IN_DIM);
    }
}

// round 4
// speedup vs baseline: 1.7513x; 1.4046x over previous
#include <cuda_runtime.h>
#include <cuda_bf16.h>
#include <cstdint>

// Problem constants
#define SLEN   2048
#define BSZ    8
#define IN_DIM 1024
#define NH     16
#define DH     64
#define NROWS  (SLEN*BSZ)              // 16384
#define NOUT   (NH*(3*DH+1))           // 3088
#define NOUT_PAD 3200                  // padded to 128-multiple for GEMM1 B rows

// ---------------- device scratch (no cudaMalloc allowed) ----------------
__device__ __nv_bfloat16 g_h_hi[(size_t)NROWS * IN_DIM];
__device__ __nv_bfloat16 g_h_lo[(size_t)NROWS * IN_DIM];
__device__ float g_qkvb[(size_t)NROWS * NOUT];
__device__ float g_q[(size_t)BSZ*NH*SLEN*DH];
__device__ float g_k[(size_t)BSZ*NH*SLEN*DH];
__device__ float g_v[(size_t)BSZ*NH*SLEN*DH];
__device__ float g_beta[(size_t)BSZ*NH*SLEN];
__device__ __nv_bfloat16 g_o_hi[(size_t)NROWS * IN_DIM];
__device__ __nv_bfloat16 g_o_lo[(size_t)NROWS * IN_DIM];
// transposed split weights: [n][k]
__device__ __nv_bfloat16 g_ws_t_hi[(size_t)NOUT_PAD * IN_DIM];
__device__ __nv_bfloat16 g_ws_t_lo[(size_t)NOUT_PAD * IN_DIM];
__device__ __nv_bfloat16 g_wo_t_hi[(size_t)IN_DIM * IN_DIM];
__device__ __nv_bfloat16 g_wo_t_lo[(size_t)IN_DIM * IN_DIM];

// ---------------- helpers ----------------
__device__ __forceinline__ void cp_async16(void* smem_dst, const void* gsrc) {
    unsigned s = (unsigned)__cvta_generic_to_shared(smem_dst);
    asm volatile("cp.async.cg.shared.global [%0], [%1], 16;\n" :: "r"(s), "l"(gsrc));
}
__device__ __forceinline__ float elu_p1(float x) {
    return x > 0.f ? x + 1.f : __expf(x);
}
__device__ __forceinline__ void split_bf16(float x, __nv_bfloat16& hi, __nv_bfloat16& lo) {
    hi = __float2bfloat16(x);
    lo = __float2bfloat16(x - __bfloat162float(hi));
}
__device__ __forceinline__ void mma_bf16(float* d, const uint32_t* a, const uint32_t* b) {
    asm volatile("mma.sync.aligned.m16n8k16.row.col.f32.bf16.bf16.f32 "
        "{%0,%1,%2,%3}, {%4,%5,%6,%7}, {%8,%9}, {%0,%1,%2,%3};"
        : "+f"(d[0]), "+f"(d[1]), "+f"(d[2]), "+f"(d[3])
        : "r"(a[0]), "r"(a[1]), "r"(a[2]), "r"(a[3]), "r"(b[0]), "r"(b[1]));
}

// ---------------- split+transpose weights: W[K][N] f32 -> T_hi/T_lo[N][K] bf16 ----------------
__global__ __launch_bounds__(256) void split_transpose(
    const float* __restrict__ W, __nv_bfloat16* __restrict__ Th,
    __nv_bfloat16* __restrict__ Tl, int K, int N)
{
    __shared__ float tile[32][33];
    int n0 = blockIdx.x * 32, k0 = blockIdx.y * 32;
    int tx = threadIdx.x, ty = threadIdx.y;   // 32 x 8
    #pragma unroll
    for (int i = 0; i < 32; i += 8) {
        int k = k0 + ty + i, n = n0 + tx;
        tile[ty + i][tx] = (n < N) ? W[(size_t)k * N + n] : 0.f;
    }
    __syncthreads();
    #pragma unroll
    for (int i = 0; i < 32; i += 8) {
        int n = n0 + ty + i, k = k0 + tx;
        if (n < N) {
            float v = tile[tx][ty + i];
            __nv_bfloat16 hi, lo;
            split_bf16(v, hi, lo);
            Th[(size_t)n * K + k] = hi;
            Tl[(size_t)n * K + k] = lo;
        }
    }
}

// ---------------- LayerNorm: one block per row; writes split bf16 ----------------
__global__ __launch_bounds__(256) void ln_kernel(
    const float* __restrict__ x, const float* __restrict__ w,
    const float* __restrict__ b, __nv_bfloat16* __restrict__ hhi,
    __nv_bfloat16* __restrict__ hlo)
{
    int row = blockIdx.x;
    int t = threadIdx.x;
    const float4* xr = (const float4*)(x + (size_t)row * IN_DIM);
    float4 v = xr[t];
    float s  = v.x + v.y + v.z + v.w;
    float ss = v.x*v.x + v.y*v.y + v.z*v.z + v.w*v.w;
    #pragma unroll
    for (int o = 16; o; o >>= 1) {
        s  += __shfl_xor_sync(0xffffffffu, s,  o);
        ss += __shfl_xor_sync(0xffffffffu, ss, o);
    }
    __shared__ float rs[8], rss[8];
    if ((t & 31) == 0) { rs[t >> 5] = s; rss[t >> 5] = ss; }
    __syncthreads();
    float S = 0.f, SS = 0.f;
    #pragma unroll
    for (int i = 0; i < 8; i++) { S += rs[i]; SS += rss[i]; }
    float mu = S * (1.f / IN_DIM);
    float var = SS * (1.f / IN_DIM) - mu * mu;
    float rstd = rsqrtf(var + 1e-5f);
    float4 wv = ((const float4*)w)[t];
    float4 bv = ((const float4*)b)[t];
    float o0 = (v.x - mu) * rstd * wv.x + bv.x;
    float o1 = (v.y - mu) * rstd * wv.y + bv.y;
    float o2 = (v.z - mu) * rstd * wv.z + bv.z;
    float o3 = (v.w - mu) * rstd * wv.w + bv.w;
    __nv_bfloat16 h0,l0,h1,l1,h2,l2,h3,l3;
    split_bf16(o0,h0,l0); split_bf16(o1,h1,l1);
    split_bf16(o2,h2,l2); split_bf16(o3,h3,l3);
    size_t base = (size_t)row * IN_DIM;
    ((__nv_bfloat162*)(hhi + base))[2*t]   = __nv_bfloat162(h0, h1);
    ((__nv_bfloat162*)(hhi + base))[2*t+1] = __nv_bfloat162(h2, h3);
    ((__nv_bfloat162*)(hlo + base))[2*t]   = __nv_bfloat162(l0, l1);
    ((__nv_bfloat162*)(hlo + base))[2*t+1] = __nv_bfloat162(l2, l3);
}

// ---------------- bf16x3 tensor-core GEMM: C = A[MxK] @ B^T (B stored [n][k]) (+Res) ----------------
// BM=128, BN=128, KT=16, 256 threads = 8 warps (2x4), warp tile 64x32.
// smem: packed bf16x2 pairs, row stride 12 uint32 (16B-aligned, conflict-free frag reads).
#define GBM 128
#define GBN 128
#define KT  16
#define SST 12

__global__ __launch_bounds__(256, 1) void gemm_bf16x3(
    const __nv_bfloat16* __restrict__ Ah, const __nv_bfloat16* __restrict__ Al,
    const __nv_bfloat16* __restrict__ Bh, const __nv_bfloat16* __restrict__ Bl,
    const float* __restrict__ Res, float* __restrict__ C,
    int M, int N, int K)
{
    __shared__ __align__(16) uint32_t sAh[2][GBM * SST];
    __shared__ __align__(16) uint32_t sAl[2][GBM * SST];
    __shared__ __align__(16) uint32_t sBh[2][GBN * SST];
    __shared__ __align__(16) uint32_t sBl[2][GBN * SST];

    const int tid  = threadIdx.x;
    const int warp = tid >> 5;
    const int lane = tid & 31;
    const int gid  = lane >> 2;
    const int tig  = lane & 3;
    const int wm   = warp & 1;    // 64 rows each
    const int wn   = warp >> 1;   // 32 cols each
    const int row0 = blockIdx.y * GBM;
    const int col0 = blockIdx.x * GBN;

    float acc[4][4][4];
    #pragma unroll
    for (int i = 0; i < 4; i++)
        #pragma unroll
        for (int j = 0; j < 4; j++)
            #pragma unroll
            for (int k = 0; k < 4; k++) acc[i][j][k] = 0.f;

    const int nk = K / KT;

    auto load_tile = [&](int kt, int buf) {
        int k0 = kt * KT;
        int m  = tid >> 1;
        int hf = tid & 1;
        size_t asrc = (size_t)(row0 + m) * K + k0 + hf * 8;
        cp_async16(&sAh[buf][m * SST + hf * 4], Ah + asrc);
        cp_async16(&sAl[buf][m * SST + hf * 4], Al + asrc);
        size_t bsrc = (size_t)(col0 + m) * K + k0 + hf * 8;
        cp_async16(&sBh[buf][m * SST + hf * 4], Bh + bsrc);
        cp_async16(&sBl[buf][m * SST + hf * 4], Bl + bsrc);
        asm volatile("cp.async.commit_group;\n" ::);
    };

    load_tile(0, 0);

    for (int kt = 0; kt < nk; kt++) {
        int buf = kt & 1;
        if (kt + 1 < nk) load_tile(kt + 1, buf ^ 1);
        else asm volatile("cp.async.commit_group;\n" ::);
        asm volatile("cp.async.wait_group 1;\n" ::);
        __syncthreads();

        uint32_t ah[4][4], al[4][4];
        #pragma unroll
        for (int mt = 0; mt < 4; mt++) {
            int r = (wm * 64 + mt * 16 + gid) * SST;
            ah[mt][0] = sAh[buf][r + tig];
            ah[mt][1] = sAh[buf][r + 8 * SST + tig];
            ah[mt][2] = sAh[buf][r + tig + 4];
            ah[mt][3] = sAh[buf][r + 8 * SST + tig + 4];
            al[mt][0] = sAl[buf][r + tig];
            al[mt][1] = sAl[buf][r + 8 * SST + tig];
            al[mt][2] = sAl[buf][r + tig + 4];
            al[mt][3] = sAl[buf][r + 8 * SST + tig + 4];
        }
        uint32_t bh[4][2], bl[4][2];
        #pragma unroll
        for (int nt = 0; nt < 4; nt++) {
            int r = (wn * 32 + nt * 8 + gid) * SST;
            bh[nt][0] = sBh[buf][r + tig];
            bh[nt][1] = sBh[buf][r + tig + 4];
            bl[nt][0] = sBl[buf][r + tig];
            bl[nt][1] = sBl[buf][r + tig + 4];
        }
        #pragma unroll
        for (int mt = 0; mt < 4; mt++)
            #pragma unroll
            for (int nt = 0; nt < 4; nt++) {
                mma_bf16(acc[mt][nt], ah[mt], bl[nt]);
                mma_bf16(acc[mt][nt], al[mt], bh[nt]);
                mma_bf16(acc[mt][nt], ah[mt], bh[nt]);
            }
        __syncthreads();
    }

    #pragma unroll
    for (int mt = 0; mt < 4; mt++) {
        #pragma unroll
        for (int nt = 0; nt < 4; nt++) {
            int r = row0 + wm * 64 + mt * 16 + gid;
            int c = col0 + wn * 32 + nt * 8 + 2 * tig;
            if (c < N) {
                size_t o0 = (size_t)r * N + c;
                size_t o1 = (size_t)(r + 8) * N + c;
                float2 v0 = make_float2(acc[mt][nt][0], acc[mt][nt][1]);
                float2 v1 = make_float2(acc[mt][nt][2], acc[mt][nt][3]);
                if (Res) {
                    float2 r0 = *(const float2*)&Res[o0];
                    float2 r1 = *(const float2*)&Res[o1];
                    v0.x += r0.x; v0.y += r0.y;
                    v1.x += r1.x; v1.y += r1.y;
                }
                *(float2*)&C[o0] = v0;
                *(float2*)&C[o1] = v1;
            }
        }
    }
}

// ---------------- transform: elu_p1+sum_norm on q,k; sigmoid beta; relayout ----------------
__global__ __launch_bounds__(256) void transform_kernel(
    const float* __restrict__ qkvb,
    float* __restrict__ Q, float* __restrict__ Kk,
    float* __restrict__ V, float* __restrict__ Beta)
{
    int gw   = blockIdx.x * 8 + (threadIdx.x >> 5);
    int lane = threadIdx.x & 31;
    int h  = gw & 15;
    int tb = gw >> 4;            // t*BSZ + b
    int b  = tb & 7;
    int t  = tb >> 3;
    const float* src = qkvb + (size_t)tb * NOUT + h * (3*DH + 1);
    size_t dst = ((size_t)(b * NH + h) * SLEN + t) * DH;

    float q0 = elu_p1(src[lane]);
    float q1 = elu_p1(src[lane + 32]);
    float s = q0 + q1;
    #pragma unroll
    for (int o = 16; o; o >>= 1) s += __shfl_xor_sync(0xffffffffu, s, o);
    float inv = 1.f / s;
    Q[dst + lane]      = q0 * inv;
    Q[dst + lane + 32] = q1 * inv;

    float k0 = elu_p1(src[64 + lane]);
    float k1 = elu_p1(src[96 + lane]);
    s = k0 + k1;
    #pragma unroll
    for (int o = 16; o; o >>= 1) s += __shfl_xor_sync(0xffffffffu, s, o);
    inv = 1.f / s;
    Kk[dst + lane]      = k0 * inv;
    Kk[dst + lane + 32] = k1 * inv;

    V[dst + lane]      = src[128 + lane];
    V[dst + lane + 32] = src[160 + lane];

    if (lane == 0) {
        float x = src[192];
        Beta[(size_t)(b * NH + h) * SLEN + t] = 1.f / (1.f + __expf(-x));
    }
}

// ---------------- delta-rule scan: one WARP per (head, 8-row octet), chunked loads ----------------
// CH=16 timesteps per cp.async group, double-buffered: one wait per 16 steps.
#define CH 16
__global__ __launch_bounds__(32) void scan_kernel(
    const float* __restrict__ Q, const float* __restrict__ Kk,
    const float* __restrict__ V, const float* __restrict__ Beta,
    __nv_bfloat16* __restrict__ Ohi, __nv_bfloat16* __restrict__ Olo)
{
    __shared__ __align__(16) float sk[2][CH][64];
    __shared__ __align__(16) float sq[2][CH][64];
    __shared__ __align__(16) float sv[2][CH][8];
    __shared__ __align__(16) float sb[2][CH];

    const int bh = blockIdx.x >> 3;   // 0..127
    const int w  = blockIdx.x & 7;    // row octet
    const int b = bh >> 4, h = bh & 15;
    const float* Kp = Kk   + (size_t)bh * SLEN * DH;
    const float* Vp = V    + (size_t)bh * SLEN * DH;
    const float* Qp = Q    + (size_t)bh * SLEN * DH;
    const float* Bp = Beta + (size_t)bh * SLEN;
    const int lane = threadIdx.x;
    const int rloc = lane >> 2;       // 0..7
    const int g = lane & 3;

    float W[16];
    #pragma unroll
    for (int m = 0; m < 16; m++) W[m] = 0.f;

    auto issue = [&](int c) {
        int buf = c & 1;
        int t0 = c * CH;
        #pragma unroll
        for (int j = 0; j < 8; j++) {
            int idx = lane + j * 32;
            int tt = idx >> 4, f = idx & 15;
            cp_async16(&sk[buf][tt][f * 4], Kp + (size_t)(t0 + tt) * DH + f * 4);
        }
        #pragma unroll
        for (int j = 0; j < 8; j++) {
            int idx = lane + j * 32;
            int tt = idx >> 4, f = idx & 15;
            cp_async16(&sq[buf][tt][f * 4], Qp + (size_t)(t0 + tt) * DH + f * 4);
        }
        {
            int tt = lane >> 1, hf = lane & 1;
            cp_async16(&sv[buf][tt][hf * 4], Vp + (size_t)(t0 + tt) * DH + w * 8 + hf * 4);
        }
        if (lane < 4) cp_async16(&sb[buf][lane * 4], Bp + t0 + lane * 4);
        asm volatile("cp.async.commit_group;\n" ::);
    };

    issue(0); issue(1);

    const int NC = SLEN / CH;  // 128
    const size_t obase = (size_t)b * IN_DIM + h * DH + w * 8 + rloc;

    for (int c = 0; c < NC; c++) {
        asm volatile("cp.async.wait_group 1;\n" ::);
        __syncwarp();
        const int buf = c & 1;

        #pragma unroll 4
        for (int tt = 0; tt < CH; tt++) {
            float kv[16], qv[16];
            #pragma unroll
            for (int m = 0; m < 4; m++) {
                float4 k4 = *(const float4*)&sk[buf][tt][g * 16 + m * 4];
                kv[m*4+0] = k4.x; kv[m*4+1] = k4.y; kv[m*4+2] = k4.z; kv[m*4+3] = k4.w;
                float4 q4 = *(const float4*)&sq[buf][tt][g * 16 + m * 4];
                qv[m*4+0] = q4.x; qv[m*4+1] = q4.y; qv[m*4+2] = q4.z; qv[m*4+3] = q4.w;
            }
            float vi   = sv[buf][tt][rloc];
            float beta = sb[buf][tt];

            // v_old[i] = sum_j W[i,j] k[j]
            float pk0 = 0.f, pk1 = 0.f, pk2 = 0.f, pk3 = 0.f;
            #pragma unroll
            for (int m = 0; m < 4; m++) {
                pk0 = fmaf(W[m],      kv[m],      pk0);
                pk1 = fmaf(W[m + 4],  kv[m + 4],  pk1);
                pk2 = fmaf(W[m + 8],  kv[m + 8],  pk2);
                pk3 = fmaf(W[m + 12], kv[m + 12], pk3);
            }
            float pk = (pk0 + pk1) + (pk2 + pk3);
            pk += __shfl_xor_sync(0xffffffffu, pk, 1);
            pk += __shfl_xor_sync(0xffffffffu, pk, 2);

            float delta = beta * (vi - pk);

            float po0 = 0.f, po1 = 0.f, po2 = 0.f, po3 = 0.f;
            #pragma unroll
            for (int m = 0; m < 4; m++) {
                W[m]      = fmaf(delta, kv[m],      W[m]);
                po0       = fmaf(W[m],  qv[m],      po0);
                W[m + 4]  = fmaf(delta, kv[m + 4],  W[m + 4]);
                po1       = fmaf(W[m + 4], qv[m + 4], po1);
                W[m + 8]  = fmaf(delta, kv[m + 8],  W[m + 8]);
                po2       = fmaf(W[m + 8], qv[m + 8], po2);
                W[m + 12] = fmaf(delta, kv[m + 12], W[m + 12]);
                po3       = fmaf(W[m + 12], qv[m + 12], po3);
            }
            float po = (po0 + po1) + (po2 + po3);
            po += __shfl_xor_sync(0xffffffffu, po, 1);
            po += __shfl_xor_sync(0xffffffffu, po, 2);

            if (g == 0) {
                int t = c * CH + tt;
                size_t off = (size_t)t * (BSZ * IN_DIM) + obase;
                __nv_bfloat16 hi, lo;
                split_bf16(po, hi, lo);
                Ohi[off] = hi;
                Olo[off] = lo;
            }
        }
        __syncwarp();
        if (c + 2 < NC) issue(c + 2);
        else asm volatile("cp.async.commit_group;\n" ::);
    }
}

// ---------------- launcher ----------------
extern "C" void kernel_launch(void* const* d_in, const int* in_sizes, int n_in,
                              void* d_out, int out_size)
{
    const float* x      = (const float*)d_in[0];
    const float* ln_w   = (const float*)d_in[1];
    const float* ln_b   = (const float*)d_in[2];
    const float* w_slow = (const float*)d_in[3];
    const float* w_out  = (const float*)d_in[4];
    float* out = (float*)d_out;

    float *p_qkvb, *p_q, *p_k, *p_v, *p_beta;
    __nv_bfloat16 *p_h_hi, *p_h_lo, *p_o_hi, *p_o_lo;
    __nv_bfloat16 *p_ws_hi, *p_ws_lo, *p_wo_hi, *p_wo_lo;
    cudaGetSymbolAddress((void**)&p_qkvb, g_qkvb);
    cudaGetSymbolAddress((void**)&p_q,    g_q);
    cudaGetSymbolAddress((void**)&p_k,    g_k);
    cudaGetSymbolAddress((void**)&p_v,    g_v);
    cudaGetSymbolAddress((void**)&p_beta, g_beta);
    cudaGetSymbolAddress((void**)&p_h_hi, g_h_hi);
    cudaGetSymbolAddress((void**)&p_h_lo, g_h_lo);
    cudaGetSymbolAddress((void**)&p_o_hi, g_o_hi);
    cudaGetSymbolAddress((void**)&p_o_lo, g_o_lo);
    cudaGetSymbolAddress((void**)&p_ws_hi, g_ws_t_hi);
    cudaGetSymbolAddress((void**)&p_ws_lo, g_ws_t_lo);
    cudaGetSymbolAddress((void**)&p_wo_hi, g_wo_t_hi);
    cudaGetSymbolAddress((void**)&p_wo_lo, g_wo_t_lo);

    // 0. split+transpose weights (tiny)
    {
        dim3 blk(32, 8);
        dim3 g1((NOUT + 31) / 32, IN_DIM / 32);
        split_transpose<<<g1, blk>>>(w_slow, p_ws_hi, p_ws_lo, IN_DIM, NOUT);
        dim3 g2(IN_DIM / 32, IN_DIM / 32);
        split_transpose<<<g2, blk>>>(w_out, p_wo_hi, p_wo_lo, IN_DIM, IN_DIM);
    }

    // 1. LayerNorm -> split bf16
    ln_kernel<<<NROWS, 256>>>(x, ln_w, ln_b, p_h_hi, p_h_lo);

    // 2. qkvb = h @ w_slow   [16384 x 3088]  (bf16x3 tensor cores)
    {
        dim3 grid(NOUT_PAD / GBN, NROWS / GBM);   // 25 x 128
        gemm_bf16x3<<<grid, 256>>>(p_h_hi, p_h_lo, p_ws_hi, p_ws_lo,
                                   nullptr, p_qkvb, NROWS, NOUT, IN_DIM);
    }

    // 3. transform -> q,k,v,beta in [bh][t][d] layout
    transform_kernel<<<(NROWS * NH) / 8, 256>>>(p_qkvb, p_q, p_k, p_v, p_beta);

    // 4. delta-rule scan (one warp per head-octet, chunked prefetch)
    scan_kernel<<<BSZ * NH * 8, 32>>>(p_q, p_k, p_v, p_beta, p_o_hi, p_o_lo);

    // 5. out = x + scan_out @ w_out   [16384 x 1024]  (bf16x3 tensor cores)
    {
        dim3 grid(IN_DIM / GBN, NROWS / GBM);     // 8 x 128
        gemm_bf16x3<<<grid, 256>>>(p_o_hi, p_o_lo, p_wo_hi, p_wo_lo,
                                   x, out, NROWS, IN_DIM, IN_DIM);
    }
}

// round 6
// speedup vs baseline: 2.2432x; 1.2809x over previous
#include <cuda_runtime.h>
#include <cuda_bf16.h>
#include <cstdint>

// Problem constants
#define SLEN   2048
#define BSZ    8
#define IN_DIM 1024
#define NH     16
#define DH     64
#define NROWS  (SLEN*BSZ)              // 16384
#define NOUT   (NH*(3*DH+1))           // 3088
#define NOUT_PAD 3200

// ---------------- device scratch ----------------
__device__ __nv_bfloat16 g_h_hi[(size_t)NROWS * IN_DIM];
__device__ __nv_bfloat16 g_h_lo[(size_t)NROWS * IN_DIM];
__device__ float g_qkvb[(size_t)NROWS * NOUT];
__device__ float g_q[(size_t)BSZ*NH*SLEN*DH];
__device__ float g_k[(size_t)BSZ*NH*SLEN*DH];
__device__ float g_v[(size_t)BSZ*NH*SLEN*DH];
__device__ float g_beta[(size_t)BSZ*NH*SLEN];
__device__ __nv_bfloat16 g_o_hi[(size_t)NROWS * IN_DIM];
__device__ __nv_bfloat16 g_o_lo[(size_t)NROWS * IN_DIM];
__device__ __nv_bfloat16 g_ws_t_hi[(size_t)NOUT_PAD * IN_DIM];
__device__ __nv_bfloat16 g_ws_t_lo[(size_t)NOUT_PAD * IN_DIM];
__device__ __nv_bfloat16 g_wo_t_hi[(size_t)IN_DIM * IN_DIM];
__device__ __nv_bfloat16 g_wo_t_lo[(size_t)IN_DIM * IN_DIM];

// ---------------- helpers ----------------
__device__ __forceinline__ void cp_async16(void* smem_dst, const void* gsrc) {
    unsigned s = (unsigned)__cvta_generic_to_shared(smem_dst);
    asm volatile("cp.async.cg.shared.global [%0], [%1], 16;\n" :: "r"(s), "l"(gsrc));
}
__device__ __forceinline__ float elu_p1(float x) {
    return x > 0.f ? x + 1.f : __expf(x);
}
__device__ __forceinline__ void split_bf16(float x, __nv_bfloat16& hi, __nv_bfloat16& lo) {
    hi = __float2bfloat16(x);
    lo = __float2bfloat16(x - __bfloat162float(hi));
}
__device__ __forceinline__ void mma_bf16(float* d, const uint32_t* a, const uint32_t* b) {
    asm volatile("mma.sync.aligned.m16n8k16.row.col.f32.bf16.bf16.f32 "
        "{%0,%1,%2,%3}, {%4,%5,%6,%7}, {%8,%9}, {%0,%1,%2,%3};"
        : "+f"(d[0]), "+f"(d[1]), "+f"(d[2]), "+f"(d[3])
        : "r"(a[0]), "r"(a[1]), "r"(a[2]), "r"(a[3]), "r"(b[0]), "r"(b[1]));
}

// ---------------- split+transpose weights: W[K][N] f32 -> T_hi/T_lo[Npad][K] bf16 ----------------
__global__ __launch_bounds__(256) void split_transpose(
    const float* __restrict__ W, __nv_bfloat16* __restrict__ Th,
    __nv_bfloat16* __restrict__ Tl, int K, int N)
{
    __shared__ float tile[32][33];
    int n0 = blockIdx.x * 32, k0 = blockIdx.y * 32;
    int tx = threadIdx.x, ty = threadIdx.y;   // 32 x 8
    #pragma unroll
    for (int i = 0; i < 32; i += 8) {
        int k = k0 + ty + i, n = n0 + tx;
        tile[ty + i][tx] = (n < N) ? W[(size_t)k * N + n] : 0.f;
    }
    __syncthreads();
    #pragma unroll
    for (int i = 0; i < 32; i += 8) {
        int n = n0 + ty + i, k = k0 + tx;
        float v = tile[tx][ty + i];           // zero for n >= N (pad)
        __nv_bfloat16 hi, lo;
        split_bf16(v, hi, lo);
        Th[(size_t)n * K + k] = hi;
        Tl[(size_t)n * K + k] = lo;
    }
}

// ---------------- LayerNorm: one block per row; writes split bf16 ----------------
__global__ __launch_bounds__(256) void ln_kernel(
    const float* __restrict__ x, const float* __restrict__ w,
    const float* __restrict__ b, __nv_bfloat16* __restrict__ hhi,
    __nv_bfloat16* __restrict__ hlo)
{
    int row = blockIdx.x;
    int t = threadIdx.x;
    const float4* xr = (const float4*)(x + (size_t)row * IN_DIM);
    float4 v = xr[t];
    float s  = v.x + v.y + v.z + v.w;
    float ss = v.x*v.x + v.y*v.y + v.z*v.z + v.w*v.w;
    #pragma unroll
    for (int o = 16; o; o >>= 1) {
        s  += __shfl_xor_sync(0xffffffffu, s,  o);
        ss += __shfl_xor_sync(0xffffffffu, ss, o);
    }
    __shared__ float rs[8], rss[8];
    if ((t & 31) == 0) { rs[t >> 5] = s; rss[t >> 5] = ss; }
    __syncthreads();
    float S = 0.f, SS = 0.f;
    #pragma unroll
    for (int i = 0; i < 8; i++) { S += rs[i]; SS += rss[i]; }
    float mu = S * (1.f / IN_DIM);
    float var = SS * (1.f / IN_DIM) - mu * mu;
    float rstd = rsqrtf(var + 1e-5f);
    float4 wv = ((const float4*)w)[t];
    float4 bv = ((const float4*)b)[t];
    float o0 = (v.x - mu) * rstd * wv.x + bv.x;
    float o1 = (v.y - mu) * rstd * wv.y + bv.y;
    float o2 = (v.z - mu) * rstd * wv.z + bv.z;
    float o3 = (v.w - mu) * rstd * wv.w + bv.w;
    __nv_bfloat16 h0,l0,h1,l1,h2,l2,h3,l3;
    split_bf16(o0,h0,l0); split_bf16(o1,h1,l1);
    split_bf16(o2,h2,l2); split_bf16(o3,h3,l3);
    size_t base = (size_t)row * IN_DIM;
    ((__nv_bfloat162*)(hhi + base))[2*t]   = __nv_bfloat162(h0, h1);
    ((__nv_bfloat162*)(hhi + base))[2*t+1] = __nv_bfloat162(h2, h3);
    ((__nv_bfloat162*)(hlo + base))[2*t]   = __nv_bfloat162(l0, l1);
    ((__nv_bfloat162*)(hlo + base))[2*t+1] = __nv_bfloat162(l2, l3);
}

// ---------------- bf16x3 tensor-core GEMM: C = A[MxK] @ B^T (B stored [n][k]) (+Res) ----------------
// BM=128, BN=128, KT=32, 256 threads = 8 warps (2x4), warp tile 64x32, 2 CTAs/SM.
// smem: packed bf16x2, row stride 20 uint32 (16B aligned, verified conflict-free).
// Dynamic smem: 2 stages x 4 arrays x (128*20*4)B = 81920B.
#define KT  32
#define SST 20
#define ARR_U32 (128 * SST)          // uint32 per array = 2560
#define STAGE_U32 (4 * ARR_U32)      // 10240

__global__ __launch_bounds__(256, 2) void gemm_bf16x3(
    const __nv_bfloat16* __restrict__ Ah, const __nv_bfloat16* __restrict__ Al,
    const __nv_bfloat16* __restrict__ Bh, const __nv_bfloat16* __restrict__ Bl,
    const float* __restrict__ Res, float* __restrict__ C,
    int N, int K)
{
    extern __shared__ __align__(16) uint32_t dsm[];

    const int tid  = threadIdx.x;
    const int warp = tid >> 5;
    const int lane = tid & 31;
    const int gid  = lane >> 2;
    const int tig  = lane & 3;
    const int wm   = warp & 1;    // 64 rows each
    const int wn   = warp >> 1;   // 32 cols each
    const int row0 = blockIdx.y * 128;
    const int col0 = blockIdx.x * 128;

    float acc[4][4][4];
    #pragma unroll
    for (int i = 0; i < 4; i++)
        #pragma unroll
        for (int j = 0; j < 4; j++)
            #pragma unroll
            for (int k = 0; k < 4; k++) acc[i][j][k] = 0.f;

    const int nk = K / KT;

    auto load_stage = [&](int kt, int buf) {
        const int k0 = kt * KT;
        uint32_t* sb = dsm + buf * STAGE_U32;
        #pragma unroll
        for (int half = 0; half < 2; half++) {
            int c2 = tid + half * 256;     // 0..511
            int r = c2 >> 2, f = c2 & 3;   // row, 16B-chunk
            size_t aoff = (size_t)(row0 + r) * K + k0 + f * 8;
            size_t boff = (size_t)(col0 + r) * K + k0 + f * 8;
            uint32_t* dst = sb + r * SST + f * 4;
            cp_async16(dst,               Ah + aoff);
            cp_async16(dst + ARR_U32,     Al + aoff);
            cp_async16(dst + 2 * ARR_U32, Bh + boff);
            cp_async16(dst + 3 * ARR_U32, Bl + boff);
        }
        asm volatile("cp.async.commit_group;\n" ::);
    };

    load_stage(0, 0);
    load_stage(1, 1);

    const int arow = wm * 64 + gid;       // + mt*16, +8
    const int bcol = wn * 32 + gid;       // + nt*8

    for (int kt = 0; kt < nk; kt++) {
        asm volatile("cp.async.wait_group 1;\n" ::);
        __syncthreads();
        const uint32_t* sb = dsm + (kt & 1) * STAGE_U32;
        const uint32_t* sAh = sb;
        const uint32_t* sAl = sb + ARR_U32;
        const uint32_t* sBh = sb + 2 * ARR_U32;
        const uint32_t* sBl = sb + 3 * ARR_U32;

        #pragma unroll
        for (int kb = 0; kb < 2; kb++) {      // two k16 chunks
            const int cofs = kb * 8 + tig;
            uint32_t ah[4][4], al[4][4];
            #pragma unroll
            for (int mt = 0; mt < 4; mt++) {
                int r0 = (arow + mt * 16) * SST;
                int r1 = r0 + 8 * SST;
                ah[mt][0] = sAh[r0 + cofs];
                ah[mt][1] = sAh[r1 + cofs];
                ah[mt][2] = sAh[r0 + cofs + 4];
                ah[mt][3] = sAh[r1 + cofs + 4];
                al[mt][0] = sAl[r0 + cofs];
                al[mt][1] = sAl[r1 + cofs];
                al[mt][2] = sAl[r0 + cofs + 4];
                al[mt][3] = sAl[r1 + cofs + 4];
            }
            // term 1: Ah * Bh   (term-major: consecutive MMAs hit distinct accs)
            #pragma unroll
            for (int nt = 0; nt < 4; nt++) {
                int rb = (bcol + nt * 8) * SST;
                uint32_t b[2] = { sBh[rb + cofs], sBh[rb + cofs + 4] };
                #pragma unroll
                for (int mt = 0; mt < 4; mt++) mma_bf16(acc[mt][nt], ah[mt], b);
            }
            // term 2: Ah * Bl
            #pragma unroll
            for (int nt = 0; nt < 4; nt++) {
                int rb = (bcol + nt * 8) * SST;
                uint32_t b[2] = { sBl[rb + cofs], sBl[rb + cofs + 4] };
                #pragma unroll
                for (int mt = 0; mt < 4; mt++) mma_bf16(acc[mt][nt], ah[mt], b);
            }
            // term 3: Al * Bh
            #pragma unroll
            for (int nt = 0; nt < 4; nt++) {
                int rb = (bcol + nt * 8) * SST;
                uint32_t b[2] = { sBh[rb + cofs], sBh[rb + cofs + 4] };
                #pragma unroll
                for (int mt = 0; mt < 4; mt++) mma_bf16(acc[mt][nt], al[mt], b);
            }
        }
        __syncthreads();
        if (kt + 2 < nk) load_stage(kt + 2, kt & 1);
        else asm volatile("cp.async.commit_group;\n" ::);
    }

    #pragma unroll
    for (int mt = 0; mt < 4; mt++) {
        #pragma unroll
        for (int nt = 0; nt < 4; nt++) {
            int r = row0 + wm * 64 + mt * 16 + gid;
            int c = col0 + wn * 32 + nt * 8 + 2 * tig;
            if (c < N) {
                size_t o0 = (size_t)r * N + c;
                size_t o1 = (size_t)(r + 8) * N + c;
                float2 v0 = make_float2(acc[mt][nt][0], acc[mt][nt][1]);
                float2 v1 = make_float2(acc[mt][nt][2], acc[mt][nt][3]);
                if (Res) {
                    float2 r0 = *(const float2*)&Res[o0];
                    float2 r1 = *(const float2*)&Res[o1];
                    v0.x += r0.x; v0.y += r0.y;
                    v1.x += r1.x; v1.y += r1.y;
                }
                *(float2*)&C[o0] = v0;
                *(float2*)&C[o1] = v1;
            }
        }
    }
}

// ---------------- transform: elu_p1+sum_norm on q,k; sigmoid beta; relayout ----------------
__global__ __launch_bounds__(256) void transform_kernel(
    const float* __restrict__ qkvb,
    float* __restrict__ Q, float* __restrict__ Kk,
    float* __restrict__ V, float* __restrict__ Beta)
{
    int gw   = blockIdx.x * 8 + (threadIdx.x >> 5);
    int lane = threadIdx.x & 31;
    int h  = gw & 15;
    int tb = gw >> 4;
    int b  = tb & 7;
    int t  = tb >> 3;
    const float* src = qkvb + (size_t)tb * NOUT + h * (3*DH + 1);
    size_t dst = ((size_t)(b * NH + h) * SLEN + t) * DH;

    float q0 = elu_p1(src[lane]);
    float q1 = elu_p1(src[lane + 32]);
    float s = q0 + q1;
    #pragma unroll
    for (int o = 16; o; o >>= 1) s += __shfl_xor_sync(0xffffffffu, s, o);
    float inv = 1.f / s;
    Q[dst + lane]      = q0 * inv;
    Q[dst + lane + 32] = q1 * inv;

    float k0 = elu_p1(src[64 + lane]);
    float k1 = elu_p1(src[96 + lane]);
    s = k0 + k1;
    #pragma unroll
    for (int o = 16; o; o >>= 1) s += __shfl_xor_sync(0xffffffffu, s, o);
    inv = 1.f / s;
    Kk[dst + lane]      = k0 * inv;
    Kk[dst + lane + 32] = k1 * inv;

    V[dst + lane]      = src[128 + lane];
    V[dst + lane + 32] = src[160 + lane];

    if (lane == 0) {
        float x = src[192];
        Beta[(size_t)(b * NH + h) * SLEN + t] = 1.f / (1.f + __expf(-x));
    }
}

// ---------------- delta-rule scan: one WARP per (head, 8-row octet), chunked loads ----------------
#define CH 16
__global__ __launch_bounds__(32) void scan_kernel(
    const float* __restrict__ Q, const float* __restrict__ Kk,
    const float* __restrict__ V, const float* __restrict__ Beta,
    __nv_bfloat16* __restrict__ Ohi, __nv_bfloat16* __restrict__ Olo)
{
    __shared__ __align__(16) float sk[2][CH][64];
    __shared__ __align__(16) float sq[2][CH][64];
    __shared__ __align__(16) float sv[2][CH][8];
    __shared__ __align__(16) float sb[2][CH];

    const int bh = blockIdx.x >> 3;
    const int w  = blockIdx.x & 7;
    const int b = bh >> 4, h = bh & 15;
    const float* Kp = Kk   + (size_t)bh * SLEN * DH;
    const float* Vp = V    + (size_t)bh * SLEN * DH;
    const float* Qp = Q    + (size_t)bh * SLEN * DH;
    const float* Bp = Beta + (size_t)bh * SLEN;
    const int lane = threadIdx.x;
    const int rloc = lane >> 2;
    const int g = lane & 3;

    float W[16];
    #pragma unroll
    for (int m = 0; m < 16; m++) W[m] = 0.f;

    auto issue = [&](int c) {
        int buf = c & 1;
        int t0 = c * CH;
        #pragma unroll
        for (int j = 0; j < 8; j++) {
            int idx = lane + j * 32;
            int tt = idx >> 4, f = idx & 15;
            cp_async16(&sk[buf][tt][f * 4], Kp + (size_t)(t0 + tt) * DH + f * 4);
        }
        #pragma unroll
        for (int j = 0; j < 8; j++) {
            int idx = lane + j * 32;
            int tt = idx >> 4, f = idx & 15;
            cp_async16(&sq[buf][tt][f * 4], Qp + (size_t)(t0 + tt) * DH + f * 4);
        }
        {
            int tt = lane >> 1, hf = lane & 1;
            cp_async16(&sv[buf][tt][hf * 4], Vp + (size_t)(t0 + tt) * DH + w * 8 + hf * 4);
        }
        if (lane < 4) cp_async16(&sb[buf][lane * 4], Bp + t0 + lane * 4);
        asm volatile("cp.async.commit_group;\n" ::);
    };

    issue(0); issue(1);

    const int NC = SLEN / CH;
    const size_t obase = (size_t)b * IN_DIM + h * DH + w * 8 + rloc;

    for (int c = 0; c < NC; c++) {
        asm volatile("cp.async.wait_group 1;\n" ::);
        __syncwarp();
        const int buf = c & 1;

        #pragma unroll 4
        for (int tt = 0; tt < CH; tt++) {
            float kv[16], qv[16];
            #pragma unroll
            for (int m = 0; m < 4; m++) {
                float4 k4 = *(const float4*)&sk[buf][tt][g * 16 + m * 4];
                kv[m*4+0] = k4.x; kv[m*4+1] = k4.y; kv[m*4+2] = k4.z; kv[m*4+3] = k4.w;
                float4 q4 = *(const float4*)&sq[buf][tt][g * 16 + m * 4];
                qv[m*4+0] = q4.x; qv[m*4+1] = q4.y; qv[m*4+2] = q4.z; qv[m*4+3] = q4.w;
            }
            float vi   = sv[buf][tt][rloc];
            float beta = sb[buf][tt];

            float pk0 = 0.f, pk1 = 0.f, pk2 = 0.f, pk3 = 0.f;
            #pragma unroll
            for (int m = 0; m < 4; m++) {
                pk0 = fmaf(W[m],      kv[m],      pk0);
                pk1 = fmaf(W[m + 4],  kv[m + 4],  pk1);
                pk2 = fmaf(W[m + 8],  kv[m + 8],  pk2);
                pk3 = fmaf(W[m + 12], kv[m + 12], pk3);
            }
            float pk = (pk0 + pk1) + (pk2 + pk3);
            pk += __shfl_xor_sync(0xffffffffu, pk, 1);
            pk += __shfl_xor_sync(0xffffffffu, pk, 2);

            float delta = beta * (vi - pk);

            float po0 = 0.f, po1 = 0.f, po2 = 0.f, po3 = 0.f;
            #pragma unroll
            for (int m = 0; m < 4; m++) {
                W[m]      = fmaf(delta, kv[m],      W[m]);
                po0       = fmaf(W[m],  qv[m],      po0);
                W[m + 4]  = fmaf(delta, kv[m + 4],  W[m + 4]);
                po1       = fmaf(W[m + 4], qv[m + 4], po1);
                W[m + 8]  = fmaf(delta, kv[m + 8],  W[m + 8]);
                po2       = fmaf(W[m + 8], qv[m + 8], po2);
                W[m + 12] = fmaf(delta, kv[m + 12], W[m + 12]);
                po3       = fmaf(W[m + 12], qv[m + 12], po3);
            }
            float po = (po0 + po1) + (po2 + po3);
            po += __shfl_xor_sync(0xffffffffu, po, 1);
            po += __shfl_xor_sync(0xffffffffu, po, 2);

            if (g == 0) {
                int t = c * CH + tt;
                size_t off = (size_t)t * (BSZ * IN_DIM) + obase;
                __nv_bfloat16 hi, lo;
                split_bf16(po, hi, lo);
                Ohi[off] = hi;
                Olo[off] = lo;
            }
        }
        __syncwarp();
        if (c + 2 < NC) issue(c + 2);
        else asm volatile("cp.async.commit_group;\n" ::);
    }
}

// ---------------- launcher ----------------
extern "C" void kernel_launch(void* const* d_in, const int* in_sizes, int n_in,
                              void* d_out, int out_size)
{
    const float* x      = (const float*)d_in[0];
    const float* ln_w   = (const float*)d_in[1];
    const float* ln_b   = (const float*)d_in[2];
    const float* w_slow = (const float*)d_in[3];
    const float* w_out  = (const float*)d_in[4];
    float* out = (float*)d_out;

    float *p_qkvb, *p_q, *p_k, *p_v, *p_beta;
    __nv_bfloat16 *p_h_hi, *p_h_lo, *p_o_hi, *p_o_lo;
    __nv_bfloat16 *p_ws_hi, *p_ws_lo, *p_wo_hi, *p_wo_lo;
    cudaGetSymbolAddress((void**)&p_qkvb, g_qkvb);
    cudaGetSymbolAddress((void**)&p_q,    g_q);
    cudaGetSymbolAddress((void**)&p_k,    g_k);
    cudaGetSymbolAddress((void**)&p_v,    g_v);
    cudaGetSymbolAddress((void**)&p_beta, g_beta);
    cudaGetSymbolAddress((void**)&p_h_hi, g_h_hi);
    cudaGetSymbolAddress((void**)&p_h_lo, g_h_lo);
    cudaGetSymbolAddress((void**)&p_o_hi, g_o_hi);
    cudaGetSymbolAddress((void**)&p_o_lo, g_o_lo);
    cudaGetSymbolAddress((void**)&p_ws_hi, g_ws_t_hi);
    cudaGetSymbolAddress((void**)&p_ws_lo, g_ws_t_lo);
    cudaGetSymbolAddress((void**)&p_wo_hi, g_wo_t_hi);
    cudaGetSymbolAddress((void**)&p_wo_lo, g_wo_t_lo);

    const int GEMM_SMEM = 2 * STAGE_U32 * 4;   // 81920 bytes
    cudaFuncSetAttribute(gemm_bf16x3, cudaFuncAttributeMaxDynamicSharedMemorySize, GEMM_SMEM);

    // 0. split+transpose weights (zero-padded to NOUT_PAD rows)
    {
        dim3 blk(32, 8);
        dim3 g1(NOUT_PAD / 32, IN_DIM / 32);
        split_transpose<<<g1, blk>>>(w_slow, p_ws_hi, p_ws_lo, IN_DIM, NOUT);
        dim3 g2(IN_DIM / 32, IN_DIM / 32);
        split_transpose<<<g2, blk>>>(w_out, p_wo_hi, p_wo_lo, IN_DIM, IN_DIM);
    }

    // 1. LayerNorm -> split bf16
    ln_kernel<<<NROWS, 256>>>(x, ln_w, ln_b, p_h_hi, p_h_lo);

    // 2. qkvb = h @ w_slow   (bf16x3 legacy tensor cores, 2 CTA/SM)
    {
        dim3 grid(NOUT_PAD / 128, NROWS / 128);   // 25 x 128
        gemm_bf16x3<<<grid, 256, GEMM_SMEM>>>(p_h_hi, p_h_lo, p_ws_hi, p_ws_lo,
                                              nullptr, p_qkvb, NOUT, IN_DIM);
    }

    // 3. transform -> q,k,v,beta in [bh][t][d] layout
    transform_kernel<<<(NROWS * NH) / 8, 256>>>(p_qkvb, p_q, p_k, p_v, p_beta);

    // 4. delta-rule scan
    scan_kernel<<<BSZ * NH * 8, 32>>>(p_q, p_k, p_v, p_beta, p_o_hi, p_o_lo);

    // 5. out = x + scan_out @ w_out   (bf16x3 legacy tensor cores)
    {
        dim3 grid(IN_DIM / 128, NROWS / 128);     // 8 x 128
        gemm_bf16x3<<<grid, 256, GEMM_SMEM>>>(p_o_hi, p_o_lo, p_wo_hi, p_wo_lo,
                                              x, out, IN_DIM, IN_DIM);
    }
}

// round 7
// speedup vs baseline: 2.2682x; 1.0111x over previous
#include <cuda_runtime.h>
#include <cuda_bf16.h>
#include <cstdint>

// Problem constants
#define SLEN   2048
#define BSZ    8
#define IN_DIM 1024
#define NH     16
#define DH     64
#define NROWS  (SLEN*BSZ)              // 16384
#define NOUT   (NH*(3*DH+1))           // 3088
#define NOUT_PAD 3200

// ---------------- device scratch ----------------
__device__ __nv_bfloat16 g_h_hi[(size_t)NROWS * IN_DIM];
__device__ __nv_bfloat16 g_h_lo[(size_t)NROWS * IN_DIM];
__device__ float g_qkvb[(size_t)NROWS * NOUT];
__device__ float g_q[(size_t)BSZ*NH*SLEN*DH];
__device__ float g_k[(size_t)BSZ*NH*SLEN*DH];
__device__ float g_v[(size_t)BSZ*NH*SLEN*DH];
__device__ float g_beta[(size_t)BSZ*NH*SLEN];
__device__ __nv_bfloat16 g_o_hi[(size_t)NROWS * IN_DIM];
__device__ __nv_bfloat16 g_o_lo[(size_t)NROWS * IN_DIM];
__device__ __nv_bfloat16 g_ws_t_hi[(size_t)NOUT_PAD * IN_DIM];
__device__ __nv_bfloat16 g_ws_t_lo[(size_t)NOUT_PAD * IN_DIM];
__device__ __nv_bfloat16 g_wo_t_hi[(size_t)IN_DIM * IN_DIM];
__device__ __nv_bfloat16 g_wo_t_lo[(size_t)IN_DIM * IN_DIM];

// ---------------- helpers ----------------
__device__ __forceinline__ void cp_async16(void* smem_dst, const void* gsrc) {
    unsigned s = (unsigned)__cvta_generic_to_shared(smem_dst);
    asm volatile("cp.async.cg.shared.global [%0], [%1], 16;\n" :: "r"(s), "l"(gsrc));
}
__device__ __forceinline__ float elu_p1(float x) {
    return x > 0.f ? x + 1.f : __expf(x);
}
__device__ __forceinline__ void split_bf16(float x, __nv_bfloat16& hi, __nv_bfloat16& lo) {
    hi = __float2bfloat16(x);
    lo = __float2bfloat16(x - __bfloat162float(hi));
}
__device__ __forceinline__ void mma_bf16(float* d, const uint32_t* a, const uint32_t* b) {
    asm volatile("mma.sync.aligned.m16n8k16.row.col.f32.bf16.bf16.f32 "
        "{%0,%1,%2,%3}, {%4,%5,%6,%7}, {%8,%9}, {%0,%1,%2,%3};"
        : "+f"(d[0]), "+f"(d[1]), "+f"(d[2]), "+f"(d[3])
        : "r"(a[0]), "r"(a[1]), "r"(a[2]), "r"(a[3]), "r"(b[0]), "r"(b[1]));
}
__device__ __forceinline__ void ldsm_x4(uint32_t* r, uint32_t saddr) {
    asm volatile("ldmatrix.sync.aligned.m8n8.x4.shared.b16 {%0,%1,%2,%3}, [%4];"
        : "=r"(r[0]), "=r"(r[1]), "=r"(r[2]), "=r"(r[3]) : "r"(saddr));
}
__device__ __forceinline__ void ldsm_x2(uint32_t* r, uint32_t saddr) {
    asm volatile("ldmatrix.sync.aligned.m8n8.x2.shared.b16 {%0,%1}, [%2];"
        : "=r"(r[0]), "=r"(r[1]) : "r"(saddr));
}

// ---------------- split+transpose weights: W[K][N] f32 -> T_hi/T_lo[Npad][K] bf16 ----------------
__global__ __launch_bounds__(256) void split_transpose(
    const float* __restrict__ W, __nv_bfloat16* __restrict__ Th,
    __nv_bfloat16* __restrict__ Tl, int K, int N)
{
    __shared__ float tile[32][33];
    int n0 = blockIdx.x * 32, k0 = blockIdx.y * 32;
    int tx = threadIdx.x, ty = threadIdx.y;   // 32 x 8
    #pragma unroll
    for (int i = 0; i < 32; i += 8) {
        int k = k0 + ty + i, n = n0 + tx;
        tile[ty + i][tx] = (n < N) ? W[(size_t)k * N + n] : 0.f;
    }
    __syncthreads();
    #pragma unroll
    for (int i = 0; i < 32; i += 8) {
        int n = n0 + ty + i, k = k0 + tx;
        float v = tile[tx][ty + i];
        __nv_bfloat16 hi, lo;
        split_bf16(v, hi, lo);
        Th[(size_t)n * K + k] = hi;
        Tl[(size_t)n * K + k] = lo;
    }
}

// ---------------- LayerNorm: one block per row; writes split bf16 ----------------
__global__ __launch_bounds__(256) void ln_kernel(
    const float* __restrict__ x, const float* __restrict__ w,
    const float* __restrict__ b, __nv_bfloat16* __restrict__ hhi,
    __nv_bfloat16* __restrict__ hlo)
{
    int row = blockIdx.x;
    int t = threadIdx.x;
    const float4* xr = (const float4*)(x + (size_t)row * IN_DIM);
    float4 v = xr[t];
    float s  = v.x + v.y + v.z + v.w;
    float ss = v.x*v.x + v.y*v.y + v.z*v.z + v.w*v.w;
    #pragma unroll
    for (int o = 16; o; o >>= 1) {
        s  += __shfl_xor_sync(0xffffffffu, s,  o);
        ss += __shfl_xor_sync(0xffffffffu, ss, o);
    }
    __shared__ float rs[8], rss[8];
    if ((t & 31) == 0) { rs[t >> 5] = s; rss[t >> 5] = ss; }
    __syncthreads();
    float S = 0.f, SS = 0.f;
    #pragma unroll
    for (int i = 0; i < 8; i++) { S += rs[i]; SS += rss[i]; }
    float mu = S * (1.f / IN_DIM);
    float var = SS * (1.f / IN_DIM) - mu * mu;
    float rstd = rsqrtf(var + 1e-5f);
    float4 wv = ((const float4*)w)[t];
    float4 bv = ((const float4*)b)[t];
    float o0 = (v.x - mu) * rstd * wv.x + bv.x;
    float o1 = (v.y - mu) * rstd * wv.y + bv.y;
    float o2 = (v.z - mu) * rstd * wv.z + bv.z;
    float o3 = (v.w - mu) * rstd * wv.w + bv.w;
    __nv_bfloat16 h0,l0,h1,l1,h2,l2,h3,l3;
    split_bf16(o0,h0,l0); split_bf16(o1,h1,l1);
    split_bf16(o2,h2,l2); split_bf16(o3,h3,l3);
    size_t base = (size_t)row * IN_DIM;
    ((__nv_bfloat162*)(hhi + base))[2*t]   = __nv_bfloat162(h0, h1);
    ((__nv_bfloat162*)(hhi + base))[2*t+1] = __nv_bfloat162(h2, h3);
    ((__nv_bfloat162*)(hlo + base))[2*t]   = __nv_bfloat162(l0, l1);
    ((__nv_bfloat162*)(hlo + base))[2*t+1] = __nv_bfloat162(l2, l3);
}

// ---------------- bf16x3 tensor-core GEMM (ldmatrix): C = A @ B^T (+Res) ----------------
// BM=128, BN=128, KT=32, 8 warps (2x4), warp tile 64x32, 2 CTAs/SM.
// smem rows: 32 bf16 (64B) + 16B pad => stride 20 uint32; LDSM-verified conflict-free.
#define KT  32
#define SST 20
#define ARR_U32 (128 * SST)          // 2560
#define STAGE_U32 (4 * ARR_U32)      // 10240

__global__ __launch_bounds__(256, 2) void gemm_bf16x3(
    const __nv_bfloat16* __restrict__ Ah, const __nv_bfloat16* __restrict__ Al,
    const __nv_bfloat16* __restrict__ Bh, const __nv_bfloat16* __restrict__ Bl,
    const float* __restrict__ Res, float* __restrict__ C,
    int N, int K)
{
    extern __shared__ __align__(16) uint32_t dsm[];

    const int tid  = threadIdx.x;
    const int warp = tid >> 5;
    const int lane = tid & 31;
    const int gid  = lane >> 2;
    const int tig  = lane & 3;
    const int wm   = warp & 1;
    const int wn   = warp >> 1;
    const int row0 = blockIdx.y * 128;
    const int col0 = blockIdx.x * 128;

    float acc[4][4][4];
    #pragma unroll
    for (int i = 0; i < 4; i++)
        #pragma unroll
        for (int j = 0; j < 4; j++)
            #pragma unroll
            for (int k = 0; k < 4; k++) acc[i][j][k] = 0.f;

    const int nk = K / KT;

    const uint32_t smem0 = (uint32_t)__cvta_generic_to_shared(dsm);

    auto load_stage = [&](int kt, int buf) {
        const int k0 = kt * KT;
        uint32_t* sb = dsm + buf * STAGE_U32;
        #pragma unroll
        for (int half = 0; half < 2; half++) {
            int c2 = tid + half * 256;
            int r = c2 >> 2, f = c2 & 3;
            size_t aoff = (size_t)(row0 + r) * K + k0 + f * 8;
            size_t boff = (size_t)(col0 + r) * K + k0 + f * 8;
            uint32_t* dst = sb + r * SST + f * 4;
            cp_async16(dst,               Ah + aoff);
            cp_async16(dst + ARR_U32,     Al + aoff);
            cp_async16(dst + 2 * ARR_U32, Bh + boff);
            cp_async16(dst + 3 * ARR_U32, Bl + boff);
        }
        asm volatile("cp.async.commit_group;\n" ::);
    };

    load_stage(0, 0);
    load_stage(1, 1);

    // ldmatrix lane addressing (byte offsets within an array)
    const int a_sub = lane >> 3;            // 0..3
    const int a_rin = lane & 7;             // 0..7
    // A x4: mrow = wm*64 + mt*16 + (sub&1)*8 + rin; kbyte = (sub>>1)*16
    const uint32_t a_base_off =
        (uint32_t)((wm * 64 + (a_sub & 1) * 8 + a_rin) * (SST * 4) + (a_sub >> 1) * 16);
    // B x2 (lanes 0..15): nrow = wn*32 + nt*8 + (lane&7); kbyte = ((lane>>3)&1)*16
    const uint32_t b_base_off =
        (uint32_t)((wn * 32 + (lane & 7)) * (SST * 4) + ((lane >> 3) & 1) * 16);

    for (int kt = 0; kt < nk; kt++) {
        asm volatile("cp.async.wait_group 1;\n" ::);
        __syncthreads();
        const uint32_t sbase = smem0 + (uint32_t)((kt & 1) * STAGE_U32 * 4);
        const uint32_t sAh = sbase;
        const uint32_t sAl = sbase + ARR_U32 * 4;
        const uint32_t sBh = sbase + 2 * ARR_U32 * 4;
        const uint32_t sBl = sbase + 3 * ARR_U32 * 4;

        #pragma unroll
        for (int kb = 0; kb < 2; kb++) {
            const uint32_t kbo = (uint32_t)(kb * 32);
            uint32_t ah[4][4], al[4][4];
            #pragma unroll
            for (int mt = 0; mt < 4; mt++) {
                uint32_t off = a_base_off + (uint32_t)(mt * 16 * SST * 4) + kbo;
                ldsm_x4(ah[mt], sAh + off);
                ldsm_x4(al[mt], sAl + off);
            }
            uint32_t bh[4][2], bl[4][2];
            #pragma unroll
            for (int nt = 0; nt < 4; nt++) {
                uint32_t off = b_base_off + (uint32_t)(nt * 8 * SST * 4) + kbo;
                ldsm_x2(bh[nt], sBh + off);
                ldsm_x2(bl[nt], sBl + off);
            }
            // term-major: acc reuse distance = 16 MMAs
            #pragma unroll
            for (int nt = 0; nt < 4; nt++)
                #pragma unroll
                for (int mt = 0; mt < 4; mt++) mma_bf16(acc[mt][nt], ah[mt], bh[nt]);
            #pragma unroll
            for (int nt = 0; nt < 4; nt++)
                #pragma unroll
                for (int mt = 0; mt < 4; mt++) mma_bf16(acc[mt][nt], al[mt], bh[nt]);
            #pragma unroll
            for (int nt = 0; nt < 4; nt++)
                #pragma unroll
                for (int mt = 0; mt < 4; mt++) mma_bf16(acc[mt][nt], ah[mt], bl[nt]);
        }
        __syncthreads();
        if (kt + 2 < nk) load_stage(kt + 2, kt & 1);
        else asm volatile("cp.async.commit_group;\n" ::);
    }

    #pragma unroll
    for (int mt = 0; mt < 4; mt++) {
        #pragma unroll
        for (int nt = 0; nt < 4; nt++) {
            int r = row0 + wm * 64 + mt * 16 + gid;
            int c = col0 + wn * 32 + nt * 8 + 2 * tig;
            if (c < N) {
                size_t o0 = (size_t)r * N + c;
                size_t o1 = (size_t)(r + 8) * N + c;
                float2 v0 = make_float2(acc[mt][nt][0], acc[mt][nt][1]);
                float2 v1 = make_float2(acc[mt][nt][2], acc[mt][nt][3]);
                if (Res) {
                    float2 r0 = *(const float2*)&Res[o0];
                    float2 r1 = *(const float2*)&Res[o1];
                    v0.x += r0.x; v0.y += r0.y;
                    v1.x += r1.x; v1.y += r1.y;
                }
                *(float2*)&C[o0] = v0;
                *(float2*)&C[o1] = v1;
            }
        }
    }
}

// ---------------- transform: elu_p1+sum_norm on q,k; sigmoid beta; relayout ----------------
__global__ __launch_bounds__(256) void transform_kernel(
    const float* __restrict__ qkvb,
    float* __restrict__ Q, float* __restrict__ Kk,
    float* __restrict__ V, float* __restrict__ Beta)
{
    int gw   = blockIdx.x * 8 + (threadIdx.x >> 5);
    int lane = threadIdx.x & 31;
    int h  = gw & 15;
    int tb = gw >> 4;
    int b  = tb & 7;
    int t  = tb >> 3;
    const float* src = qkvb + (size_t)tb * NOUT + h * (3*DH + 1);
    size_t dst = ((size_t)(b * NH + h) * SLEN + t) * DH;

    float q0 = elu_p1(src[lane]);
    float q1 = elu_p1(src[lane + 32]);
    float s = q0 + q1;
    #pragma unroll
    for (int o = 16; o; o >>= 1) s += __shfl_xor_sync(0xffffffffu, s, o);
    float inv = 1.f / s;
    Q[dst + lane]      = q0 * inv;
    Q[dst + lane + 32] = q1 * inv;

    float k0 = elu_p1(src[64 + lane]);
    float k1 = elu_p1(src[96 + lane]);
    s = k0 + k1;
    #pragma unroll
    for (int o = 16; o; o >>= 1) s += __shfl_xor_sync(0xffffffffu, s, o);
    inv = 1.f / s;
    Kk[dst + lane]      = k0 * inv;
    Kk[dst + lane + 32] = k1 * inv;

    V[dst + lane]      = src[128 + lane];
    V[dst + lane + 32] = src[160 + lane];

    if (lane == 0) {
        float x = src[192];
        Beta[(size_t)(b * NH + h) * SLEN + t] = 1.f / (1.f + __expf(-x));
    }
}

// ---------------- delta-rule scan: one WARP per (head, 8-row octet), chunked loads ----------------
#define CH 16
__global__ __launch_bounds__(32) void scan_kernel(
    const float* __restrict__ Q, const float* __restrict__ Kk,
    const float* __restrict__ V, const float* __restrict__ Beta,
    __nv_bfloat16* __restrict__ Ohi, __nv_bfloat16* __restrict__ Olo)
{
    __shared__ __align__(16) float sk[2][CH][64];
    __shared__ __align__(16) float sq[2][CH][64];
    __shared__ __align__(16) float sv[2][CH][8];
    __shared__ __align__(16) float sb[2][CH];

    const int bh = blockIdx.x >> 3;
    const int w  = blockIdx.x & 7;
    const int b = bh >> 4, h = bh & 15;
    const float* Kp = Kk   + (size_t)bh * SLEN * DH;
    const float* Vp = V    + (size_t)bh * SLEN * DH;
    const float* Qp = Q    + (size_t)bh * SLEN * DH;
    const float* Bp = Beta + (size_t)bh * SLEN;
    const int lane = threadIdx.x;
    const int rloc = lane >> 2;
    const int g = lane & 3;

    float W[16];
    #pragma unroll
    for (int m = 0; m < 16; m++) W[m] = 0.f;

    auto issue = [&](int c) {
        int buf = c & 1;
        int t0 = c * CH;
        #pragma unroll
        for (int j = 0; j < 8; j++) {
            int idx = lane + j * 32;
            int tt = idx >> 4, f = idx & 15;
            cp_async16(&sk[buf][tt][f * 4], Kp + (size_t)(t0 + tt) * DH + f * 4);
        }
        #pragma unroll
        for (int j = 0; j < 8; j++) {
            int idx = lane + j * 32;
            int tt = idx >> 4, f = idx & 15;
            cp_async16(&sq[buf][tt][f * 4], Qp + (size_t)(t0 + tt) * DH + f * 4);
        }
        {
            int tt = lane >> 1, hf = lane & 1;
            cp_async16(&sv[buf][tt][hf * 4], Vp + (size_t)(t0 + tt) * DH + w * 8 + hf * 4);
        }
        if (lane < 4) cp_async16(&sb[buf][lane * 4], Bp + t0 + lane * 4);
        asm volatile("cp.async.commit_group;\n" ::);
    };

    issue(0); issue(1);

    const int NC = SLEN / CH;
    const size_t obase = (size_t)b * IN_DIM + h * DH + w * 8 + rloc;

    for (int c = 0; c < NC; c++) {
        asm volatile("cp.async.wait_group 1;\n" ::);
        __syncwarp();
        const int buf = c & 1;

        #pragma unroll 4
        for (int tt = 0; tt < CH; tt++) {
            float kv[16], qv[16];
            #pragma unroll
            for (int m = 0; m < 4; m++) {
                float4 k4 = *(const float4*)&sk[buf][tt][g * 16 + m * 4];
                kv[m*4+0] = k4.x; kv[m*4+1] = k4.y; kv[m*4+2] = k4.z; kv[m*4+3] = k4.w;
                float4 q4 = *(const float4*)&sq[buf][tt][g * 16 + m * 4];
                qv[m*4+0] = q4.x; qv[m*4+1] = q4.y; qv[m*4+2] = q4.z; qv[m*4+3] = q4.w;
            }
            float vi   = sv[buf][tt][rloc];
            float beta = sb[buf][tt];

            float pk0 = 0.f, pk1 = 0.f, pk2 = 0.f, pk3 = 0.f;
            #pragma unroll
            for (int m = 0; m < 4; m++) {
                pk0 = fmaf(W[m],      kv[m],      pk0);
                pk1 = fmaf(W[m + 4],  kv[m + 4],  pk1);
                pk2 = fmaf(W[m + 8],  kv[m + 8],  pk2);
                pk3 = fmaf(W[m + 12], kv[m + 12], pk3);
            }
            float pk = (pk0 + pk1) + (pk2 + pk3);
            pk += __shfl_xor_sync(0xffffffffu, pk, 1);
            pk += __shfl_xor_sync(0xffffffffu, pk, 2);

            float delta = beta * (vi - pk);

            float po0 = 0.f, po1 = 0.f, po2 = 0.f, po3 = 0.f;
            #pragma unroll
            for (int m = 0; m < 4; m++) {
                W[m]      = fmaf(delta, kv[m],      W[m]);
                po0       = fmaf(W[m],  qv[m],      po0);
                W[m + 4]  = fmaf(delta, kv[m + 4],  W[m + 4]);
                po1       = fmaf(W[m + 4], qv[m + 4], po1);
                W[m + 8]  = fmaf(delta, kv[m + 8],  W[m + 8]);
                po2       = fmaf(W[m + 8], qv[m + 8], po2);
                W[m + 12] = fmaf(delta, kv[m + 12], W[m + 12]);
                po3       = fmaf(W[m + 12], qv[m + 12], po3);
            }
            float po = (po0 + po1) + (po2 + po3);
            po += __shfl_xor_sync(0xffffffffu, po, 1);
            po += __shfl_xor_sync(0xffffffffu, po, 2);

            if (g == 0) {
                int t = c * CH + tt;
                size_t off = (size_t)t * (BSZ * IN_DIM) + obase;
                __nv_bfloat16 hi, lo;
                split_bf16(po, hi, lo);
                Ohi[off] = hi;
                Olo[off] = lo;
            }
        }
        __syncwarp();
        if (c + 2 < NC) issue(c + 2);
        else asm volatile("cp.async.commit_group;\n" ::);
    }
}

// ---------------- launcher ----------------
extern "C" void kernel_launch(void* const* d_in, const int* in_sizes, int n_in,
                              void* d_out, int out_size)
{
    const float* x      = (const float*)d_in[0];
    const float* ln_w   = (const float*)d_in[1];
    const float* ln_b   = (const float*)d_in[2];
    const float* w_slow = (const float*)d_in[3];
    const float* w_out  = (const float*)d_in[4];
    float* out = (float*)d_out;

    float *p_qkvb, *p_q, *p_k, *p_v, *p_beta;
    __nv_bfloat16 *p_h_hi, *p_h_lo, *p_o_hi, *p_o_lo;
    __nv_bfloat16 *p_ws_hi, *p_ws_lo, *p_wo_hi, *p_wo_lo;
    cudaGetSymbolAddress((void**)&p_qkvb, g_qkvb);
    cudaGetSymbolAddress((void**)&p_q,    g_q);
    cudaGetSymbolAddress((void**)&p_k,    g_k);
    cudaGetSymbolAddress((void**)&p_v,    g_v);
    cudaGetSymbolAddress((void**)&p_beta, g_beta);
    cudaGetSymbolAddress((void**)&p_h_hi, g_h_hi);
    cudaGetSymbolAddress((void**)&p_h_lo, g_h_lo);
    cudaGetSymbolAddress((void**)&p_o_hi, g_o_hi);
    cudaGetSymbolAddress((void**)&p_o_lo, g_o_lo);
    cudaGetSymbolAddress((void**)&p_ws_hi, g_ws_t_hi);
    cudaGetSymbolAddress((void**)&p_ws_lo, g_ws_t_lo);
    cudaGetSymbolAddress((void**)&p_wo_hi, g_wo_t_hi);
    cudaGetSymbolAddress((void**)&p_wo_lo, g_wo_t_lo);

    const int GEMM_SMEM = 2 * STAGE_U32 * 4;   // 81920 bytes
    cudaFuncSetAttribute(gemm_bf16x3, cudaFuncAttributeMaxDynamicSharedMemorySize, GEMM_SMEM);

    // 0. split+transpose weights (zero-padded to NOUT_PAD rows)
    {
        dim3 blk(32, 8);
        dim3 g1(NOUT_PAD / 32, IN_DIM / 32);
        split_transpose<<<g1, blk>>>(w_slow, p_ws_hi, p_ws_lo, IN_DIM, NOUT);
        dim3 g2(IN_DIM / 32, IN_DIM / 32);
        split_transpose<<<g2, blk>>>(w_out, p_wo_hi, p_wo_lo, IN_DIM, IN_DIM);
    }

    // 1. LayerNorm -> split bf16
    ln_kernel<<<NROWS, 256>>>(x, ln_w, ln_b, p_h_hi, p_h_lo);

    // 2. qkvb = h @ w_slow   (bf16x3, ldmatrix)
    {
        dim3 grid(NOUT_PAD / 128, NROWS / 128);   // 25 x 128
        gemm_bf16x3<<<grid, 256, GEMM_SMEM>>>(p_h_hi, p_h_lo, p_ws_hi, p_ws_lo,
                                              nullptr, p_qkvb, NOUT, IN_DIM);
    }

    // 3. transform -> q,k,v,beta in [bh][t][d] layout
    transform_kernel<<<(NROWS * NH) / 8, 256>>>(p_qkvb, p_q, p_k, p_v, p_beta);

    // 4. delta-rule scan
    scan_kernel<<<BSZ * NH * 8, 32>>>(p_q, p_k, p_v, p_beta, p_o_hi, p_o_lo);

    // 5. out = x + scan_out @ w_out   (bf16x3, ldmatrix)
    {
        dim3 grid(IN_DIM / 128, NROWS / 128);     // 8 x 128
        gemm_bf16x3<<<grid, 256, GEMM_SMEM>>>(p_o_hi, p_o_lo, p_wo_hi, p_wo_lo,
                                              x, out, IN_DIM, IN_DIM);
    }
}

// round 8
// speedup vs baseline: 2.5426x; 1.1210x over previous
#include <cuda_runtime.h>
#include <cuda_bf16.h>
#include <cstdint>

// Problem constants
#define SLEN   2048
#define BSZ    8
#define IN_DIM 1024
#define NH     16
#define DH     64
#define NROWS  (SLEN*BSZ)              // 16384
#define NOUT   (NH*(3*DH+1))           // 3088
#define NOUT_PAD 3200

// ---------------- device scratch ----------------
__device__ __nv_bfloat16 g_h_hi[(size_t)NROWS * IN_DIM];
__device__ __nv_bfloat16 g_h_lo[(size_t)NROWS * IN_DIM];
__device__ float g_qkvb[(size_t)NROWS * NOUT];
__device__ float g_q[(size_t)BSZ*NH*SLEN*DH];
__device__ float g_k[(size_t)BSZ*NH*SLEN*DH];
__device__ float g_v[(size_t)BSZ*NH*SLEN*DH];
__device__ float g_beta[(size_t)BSZ*NH*SLEN];
__device__ __nv_bfloat16 g_o_hi[(size_t)NROWS * IN_DIM];
__device__ __nv_bfloat16 g_o_lo[(size_t)NROWS * IN_DIM];
__device__ __nv_bfloat16 g_ws_t_hi[(size_t)NOUT_PAD * IN_DIM];
__device__ __nv_bfloat16 g_ws_t_lo[(size_t)NOUT_PAD * IN_DIM];
__device__ __nv_bfloat16 g_wo_t_hi[(size_t)IN_DIM * IN_DIM];
__device__ __nv_bfloat16 g_wo_t_lo[(size_t)IN_DIM * IN_DIM];

// ---------------- helpers ----------------
__device__ __forceinline__ void cp_async16(void* smem_dst, const void* gsrc) {
    unsigned s = (unsigned)__cvta_generic_to_shared(smem_dst);
    asm volatile("cp.async.cg.shared.global [%0], [%1], 16;\n" :: "r"(s), "l"(gsrc));
}
__device__ __forceinline__ float elu_p1(float x) {
    return x > 0.f ? x + 1.f : __expf(x);
}
__device__ __forceinline__ void split_bf16(float x, __nv_bfloat16& hi, __nv_bfloat16& lo) {
    hi = __float2bfloat16(x);
    lo = __float2bfloat16(x - __bfloat162float(hi));
}
__device__ __forceinline__ void mma_bf16(float* d, const uint32_t* a, const uint32_t* b) {
    asm volatile("mma.sync.aligned.m16n8k16.row.col.f32.bf16.bf16.f32 "
        "{%0,%1,%2,%3}, {%4,%5,%6,%7}, {%8,%9}, {%0,%1,%2,%3};"
        : "+f"(d[0]), "+f"(d[1]), "+f"(d[2]), "+f"(d[3])
        : "r"(a[0]), "r"(a[1]), "r"(a[2]), "r"(a[3]), "r"(b[0]), "r"(b[1]));
}
__device__ __forceinline__ void ldsm_x4(uint32_t* r, uint32_t saddr) {
    asm volatile("ldmatrix.sync.aligned.m8n8.x4.shared.b16 {%0,%1,%2,%3}, [%4];"
        : "=r"(r[0]), "=r"(r[1]), "=r"(r[2]), "=r"(r[3]) : "r"(saddr));
}
__device__ __forceinline__ void ldsm_x2(uint32_t* r, uint32_t saddr) {
    asm volatile("ldmatrix.sync.aligned.m8n8.x2.shared.b16 {%0,%1}, [%2];"
        : "=r"(r[0]), "=r"(r[1]) : "r"(saddr));
}

// ---------------- split+transpose weights: W[K][N] f32 -> T_hi/T_lo[Npad][K] bf16 ----------------
__global__ __launch_bounds__(256) void split_transpose(
    const float* __restrict__ W, __nv_bfloat16* __restrict__ Th,
    __nv_bfloat16* __restrict__ Tl, int K, int N)
{
    __shared__ float tile[32][33];
    int n0 = blockIdx.x * 32, k0 = blockIdx.y * 32;
    int tx = threadIdx.x, ty = threadIdx.y;   // 32 x 8
    #pragma unroll
    for (int i = 0; i < 32; i += 8) {
        int k = k0 + ty + i, n = n0 + tx;
        tile[ty + i][tx] = (n < N) ? W[(size_t)k * N + n] : 0.f;
    }
    __syncthreads();
    #pragma unroll
    for (int i = 0; i < 32; i += 8) {
        int n = n0 + ty + i, k = k0 + tx;
        float v = tile[tx][ty + i];
        __nv_bfloat16 hi, lo;
        split_bf16(v, hi, lo);
        Th[(size_t)n * K + k] = hi;
        Tl[(size_t)n * K + k] = lo;
    }
}

// ---------------- LayerNorm: one block per row; writes split bf16 ----------------
__global__ __launch_bounds__(256) void ln_kernel(
    const float* __restrict__ x, const float* __restrict__ w,
    const float* __restrict__ b, __nv_bfloat16* __restrict__ hhi,
    __nv_bfloat16* __restrict__ hlo)
{
    int row = blockIdx.x;
    int t = threadIdx.x;
    const float4* xr = (const float4*)(x + (size_t)row * IN_DIM);
    float4 v = xr[t];
    float s  = v.x + v.y + v.z + v.w;
    float ss = v.x*v.x + v.y*v.y + v.z*v.z + v.w*v.w;
    #pragma unroll
    for (int o = 16; o; o >>= 1) {
        s  += __shfl_xor_sync(0xffffffffu, s,  o);
        ss += __shfl_xor_sync(0xffffffffu, ss, o);
    }
    __shared__ float rs[8], rss[8];
    if ((t & 31) == 0) { rs[t >> 5] = s; rss[t >> 5] = ss; }
    __syncthreads();
    float S = 0.f, SS = 0.f;
    #pragma unroll
    for (int i = 0; i < 8; i++) { S += rs[i]; SS += rss[i]; }
    float mu = S * (1.f / IN_DIM);
    float var = SS * (1.f / IN_DIM) - mu * mu;
    float rstd = rsqrtf(var + 1e-5f);
    float4 wv = ((const float4*)w)[t];
    float4 bv = ((const float4*)b)[t];
    float o0 = (v.x - mu) * rstd * wv.x + bv.x;
    float o1 = (v.y - mu) * rstd * wv.y + bv.y;
    float o2 = (v.z - mu) * rstd * wv.z + bv.z;
    float o3 = (v.w - mu) * rstd * wv.w + bv.w;
    __nv_bfloat16 h0,l0,h1,l1,h2,l2,h3,l3;
    split_bf16(o0,h0,l0); split_bf16(o1,h1,l1);
    split_bf16(o2,h2,l2); split_bf16(o3,h3,l3);
    size_t base = (size_t)row * IN_DIM;
    ((__nv_bfloat162*)(hhi + base))[2*t]   = __nv_bfloat162(h0, h1);
    ((__nv_bfloat162*)(hhi + base))[2*t+1] = __nv_bfloat162(h2, h3);
    ((__nv_bfloat162*)(hlo + base))[2*t]   = __nv_bfloat162(l0, l1);
    ((__nv_bfloat162*)(hlo + base))[2*t+1] = __nv_bfloat162(l2, l3);
}

// ---------------- bf16x3 tensor-core GEMM (ldmatrix, XOR-swizzle, 3-stage) ----------------
// C = A[MxK] @ B^T (B stored [n][k]) (+Res). BM=BN=128, KT=32, 8 warps, 2 CTAs/SM.
// smem array: 128 rows x 64B (16 u32/row), phys 16B-chunk = logical ^ ((row>>1)&3).
// LDSM 8-address groups verified bijective over bank-groups. One __syncthreads per kt.
#define KT  32
#define ARR_U32 (128 * 16)           // 2048 u32 = 8KB per array
#define STAGE_U32 (4 * ARR_U32)      // 32KB per stage
#define GEMM_SMEM_BYTES (3 * STAGE_U32 * 4)   // 98304

__global__ __launch_bounds__(256, 2) void gemm_bf16x3(
    const __nv_bfloat16* __restrict__ Ah, const __nv_bfloat16* __restrict__ Al,
    const __nv_bfloat16* __restrict__ Bh, const __nv_bfloat16* __restrict__ Bl,
    const float* __restrict__ Res, float* __restrict__ C,
    int N, int K)
{
    extern __shared__ __align__(16) uint32_t dsm[];

    const int tid  = threadIdx.x;
    const int warp = tid >> 5;
    const int lane = tid & 31;
    const int gid  = lane >> 2;
    const int tig  = lane & 3;
    const int wm   = warp & 1;
    const int wn   = warp >> 1;
    const int row0 = blockIdx.y * 128;
    const int col0 = blockIdx.x * 128;

    float acc[4][4][4];
    #pragma unroll
    for (int i = 0; i < 4; i++)
        #pragma unroll
        for (int j = 0; j < 4; j++)
            #pragma unroll
            for (int k = 0; k < 4; k++) acc[i][j][k] = 0.f;

    const int nk = K / KT;
    const uint32_t smem0 = (uint32_t)__cvta_generic_to_shared(dsm);

    // cp.async swizzled destination (per thread, per half)
    auto load_stage = [&](int kt) {
        const int k0 = kt * KT;
        uint32_t* sb = dsm + (kt % 3) * STAGE_U32;
        #pragma unroll
        for (int half = 0; half < 2; half++) {
            int c2 = tid + half * 256;         // 0..511
            int r = c2 >> 2, f = c2 & 3;       // row, logical 16B chunk
            int fs = f ^ ((r >> 1) & 3);       // physical chunk
            size_t aoff = (size_t)(row0 + r) * K + k0 + f * 8;
            size_t boff = (size_t)(col0 + r) * K + k0 + f * 8;
            uint32_t* dst = sb + r * 16 + fs * 4;
            cp_async16(dst,               Ah + aoff);
            cp_async16(dst + ARR_U32,     Al + aoff);
            cp_async16(dst + 2 * ARR_U32, Bh + boff);
            cp_async16(dst + 3 * ARR_U32, Bl + boff);
        }
        asm volatile("cp.async.commit_group;\n" ::);
    };

    load_stage(0);
    load_stage(1);

    // --- ldmatrix lane addressing ---
    // A x4: row = wm*64 + mt*16 + (sub&1)*8 + rin;  logical chunk = kb*2 + (sub>>1)
    // swizzle phase (row>>1)&3 invariant under mt*16 steps.
    const int a_sub = lane >> 3;
    const int a_rin = lane & 7;
    const int a_row0 = wm * 64 + (a_sub & 1) * 8 + a_rin;
    const int a_ph  = (a_row0 >> 1) & 3;
    const uint32_t a_byte0 = (uint32_t)(a_row0 * 64);
    const uint32_t a_ch[2] = { (uint32_t)((((a_sub >> 1)    ) ^ a_ph) * 16),
                               (uint32_t)(((2 + (a_sub >> 1)) ^ a_ph) * 16) };
    // B x2 (lanes 0..15): row = wn*32 + nt*8 + (lane&7); chunk = kb*2 + ((lane>>3)&1)
    const int b_row0 = wn * 32 + (lane & 7);
    const int b_ph  = (b_row0 >> 1) & 3;
    const uint32_t b_byte0 = (uint32_t)(b_row0 * 64);
    const int b_sub = (lane >> 3) & 1;
    const uint32_t b_ch[2] = { (uint32_t)(((b_sub    ) ^ b_ph) * 16),
                               (uint32_t)(((2 + b_sub) ^ b_ph) * 16) };

    for (int kt = 0; kt < nk; kt++) {
        asm volatile("cp.async.wait_group 1;\n" ::);
        __syncthreads();
        // issue next loads FIRST (overlap with MMA block); buffer (kt+2)%3 was
        // last read at kt-1, protected by the sync above.
        if (kt + 2 < nk) load_stage(kt + 2);
        else asm volatile("cp.async.commit_group;\n" ::);

        const uint32_t sbase = smem0 + (uint32_t)((kt % 3) * STAGE_U32 * 4);
        const uint32_t sAh = sbase;
        const uint32_t sAl = sbase + ARR_U32 * 4;
        const uint32_t sBh = sbase + 2 * ARR_U32 * 4;
        const uint32_t sBl = sbase + 3 * ARR_U32 * 4;

        #pragma unroll
        for (int kb = 0; kb < 2; kb++) {
            uint32_t ah[4][4], al[4][4];
            #pragma unroll
            for (int mt = 0; mt < 4; mt++) {
                uint32_t off = a_byte0 + (uint32_t)(mt * 16 * 64) + a_ch[kb];
                ldsm_x4(ah[mt], sAh + off);
                ldsm_x4(al[mt], sAl + off);
            }
            uint32_t bh[4][2], bl[4][2];
            #pragma unroll
            for (int nt = 0; nt < 4; nt++) {
                uint32_t off = b_byte0 + (uint32_t)(nt * 8 * 64) + b_ch[kb];
                ldsm_x2(bh[nt], sBh + off);
                ldsm_x2(bl[nt], sBl + off);
            }
            #pragma unroll
            for (int nt = 0; nt < 4; nt++)
                #pragma unroll
                for (int mt = 0; mt < 4; mt++) mma_bf16(acc[mt][nt], ah[mt], bh[nt]);
            #pragma unroll
            for (int nt = 0; nt < 4; nt++)
                #pragma unroll
                for (int mt = 0; mt < 4; mt++) mma_bf16(acc[mt][nt], al[mt], bh[nt]);
            #pragma unroll
            for (int nt = 0; nt < 4; nt++)
                #pragma unroll
                for (int mt = 0; mt < 4; mt++) mma_bf16(acc[mt][nt], ah[mt], bl[nt]);
        }
    }

    #pragma unroll
    for (int mt = 0; mt < 4; mt++) {
        #pragma unroll
        for (int nt = 0; nt < 4; nt++) {
            int r = row0 + wm * 64 + mt * 16 + gid;
            int c = col0 + wn * 32 + nt * 8 + 2 * tig;
            if (c < N) {
                size_t o0 = (size_t)r * N + c;
                size_t o1 = (size_t)(r + 8) * N + c;
                float2 v0 = make_float2(acc[mt][nt][0], acc[mt][nt][1]);
                float2 v1 = make_float2(acc[mt][nt][2], acc[mt][nt][3]);
                if (Res) {
                    float2 r0 = *(const float2*)&Res[o0];
                    float2 r1 = *(const float2*)&Res[o1];
                    v0.x += r0.x; v0.y += r0.y;
                    v1.x += r1.x; v1.y += r1.y;
                }
                *(float2*)&C[o0] = v0;
                *(float2*)&C[o1] = v1;
            }
        }
    }
}

// ---------------- transform: elu_p1+sum_norm on q,k; sigmoid beta; relayout ----------------
__global__ __launch_bounds__(256) void transform_kernel(
    const float* __restrict__ qkvb,
    float* __restrict__ Q, float* __restrict__ Kk,
    float* __restrict__ V, float* __restrict__ Beta)
{
    int gw   = blockIdx.x * 8 + (threadIdx.x >> 5);
    int lane = threadIdx.x & 31;
    int h  = gw & 15;
    int tb = gw >> 4;
    int b  = tb & 7;
    int t  = tb >> 3;
    const float* src = qkvb + (size_t)tb * NOUT + h * (3*DH + 1);
    size_t dst = ((size_t)(b * NH + h) * SLEN + t) * DH;

    float q0 = elu_p1(src[lane]);
    float q1 = elu_p1(src[lane + 32]);
    float s = q0 + q1;
    #pragma unroll
    for (int o = 16; o; o >>= 1) s += __shfl_xor_sync(0xffffffffu, s, o);
    float inv = 1.f / s;
    Q[dst + lane]      = q0 * inv;
    Q[dst + lane + 32] = q1 * inv;

    float k0 = elu_p1(src[64 + lane]);
    float k1 = elu_p1(src[96 + lane]);
    s = k0 + k1;
    #pragma unroll
    for (int o = 16; o; o >>= 1) s += __shfl_xor_sync(0xffffffffu, s, o);
    inv = 1.f / s;
    Kk[dst + lane]      = k0 * inv;
    Kk[dst + lane + 32] = k1 * inv;

    V[dst + lane]      = src[128 + lane];
    V[dst + lane + 32] = src[160 + lane];

    if (lane == 0) {
        float x = src[192];
        Beta[(size_t)(b * NH + h) * SLEN + t] = 1.f / (1.f + __expf(-x));
    }
}

// ---------------- delta-rule scan: one WARP per (head, 8-row octet), chunked loads ----------------
#define CH 16
__global__ __launch_bounds__(32) void scan_kernel(
    const float* __restrict__ Q, const float* __restrict__ Kk,
    const float* __restrict__ V, const float* __restrict__ Beta,
    __nv_bfloat16* __restrict__ Ohi, __nv_bfloat16* __restrict__ Olo)
{
    __shared__ __align__(16) float sk[2][CH][64];
    __shared__ __align__(16) float sq[2][CH][64];
    __shared__ __align__(16) float sv[2][CH][8];
    __shared__ __align__(16) float sb[2][CH];

    const int bh = blockIdx.x >> 3;
    const int w  = blockIdx.x & 7;
    const int b = bh >> 4, h = bh & 15;
    const float* Kp = Kk   + (size_t)bh * SLEN * DH;
    const float* Vp = V    + (size_t)bh * SLEN * DH;
    const float* Qp = Q    + (size_t)bh * SLEN * DH;
    const float* Bp = Beta + (size_t)bh * SLEN;
    const int lane = threadIdx.x;
    const int rloc = lane >> 2;
    const int g = lane & 3;

    float W[16];
    #pragma unroll
    for (int m = 0; m < 16; m++) W[m] = 0.f;

    auto issue = [&](int c) {
        int buf = c & 1;
        int t0 = c * CH;
        #pragma unroll
        for (int j = 0; j < 8; j++) {
            int idx = lane + j * 32;
            int tt = idx >> 4, f = idx & 15;
            cp_async16(&sk[buf][tt][f * 4], Kp + (size_t)(t0 + tt) * DH + f * 4);
        }
        #pragma unroll
        for (int j = 0; j < 8; j++) {
            int idx = lane + j * 32;
            int tt = idx >> 4, f = idx & 15;
            cp_async16(&sq[buf][tt][f * 4], Qp + (size_t)(t0 + tt) * DH + f * 4);
        }
        {
            int tt = lane >> 1, hf = lane & 1;
            cp_async16(&sv[buf][tt][hf * 4], Vp + (size_t)(t0 + tt) * DH + w * 8 + hf * 4);
        }
        if (lane < 4) cp_async16(&sb[buf][lane * 4], Bp + t0 + lane * 4);
        asm volatile("cp.async.commit_group;\n" ::);
    };

    issue(0); issue(1);

    const int NC = SLEN / CH;
    const size_t obase = (size_t)b * IN_DIM + h * DH + w * 8 + rloc;

    for (int c = 0; c < NC; c++) {
        asm volatile("cp.async.wait_group 1;\n" ::);
        __syncwarp();
        const int buf = c & 1;

        #pragma unroll 4
        for (int tt = 0; tt < CH; tt++) {
            float kv[16], qv[16];
            #pragma unroll
            for (int m = 0; m < 4; m++) {
                float4 k4 = *(const float4*)&sk[buf][tt][g * 16 + m * 4];
                kv[m*4+0] = k4.x; kv[m*4+1] = k4.y; kv[m*4+2] = k4.z; kv[m*4+3] = k4.w;
                float4 q4 = *(const float4*)&sq[buf][tt][g * 16 + m * 4];
                qv[m*4+0] = q4.x; qv[m*4+1] = q4.y; qv[m*4+2] = q4.z; qv[m*4+3] = q4.w;
            }
            float vi   = sv[buf][tt][rloc];
            float beta = sb[buf][tt];

            float pk0 = 0.f, pk1 = 0.f, pk2 = 0.f, pk3 = 0.f;
            #pragma unroll
            for (int m = 0; m < 4; m++) {
                pk0 = fmaf(W[m],      kv[m],      pk0);
                pk1 = fmaf(W[m + 4],  kv[m + 4],  pk1);
                pk2 = fmaf(W[m + 8],  kv[m + 8],  pk2);
                pk3 = fmaf(W[m + 12], kv[m + 12], pk3);
            }
            float pk = (pk0 + pk1) + (pk2 + pk3);
            pk += __shfl_xor_sync(0xffffffffu, pk, 1);
            pk += __shfl_xor_sync(0xffffffffu, pk, 2);

            float delta = beta * (vi - pk);

            float po0 = 0.f, po1 = 0.f, po2 = 0.f, po3 = 0.f;
            #pragma unroll
            for (int m = 0; m < 4; m++) {
                W[m]      = fmaf(delta, kv[m],      W[m]);
                po0       = fmaf(W[m],  qv[m],      po0);
                W[m + 4]  = fmaf(delta, kv[m + 4],  W[m + 4]);
                po1       = fmaf(W[m + 4], qv[m + 4], po1);
                W[m + 8]  = fmaf(delta, kv[m + 8],  W[m + 8]);
                po2       = fmaf(W[m + 8], qv[m + 8], po2);
                W[m + 12] = fmaf(delta, kv[m + 12], W[m + 12]);
                po3       = fmaf(W[m + 12], qv[m + 12], po3);
            }
            float po = (po0 + po1) + (po2 + po3);
            po += __shfl_xor_sync(0xffffffffu, po, 1);
            po += __shfl_xor_sync(0xffffffffu, po, 2);

            if (g == 0) {
                int t = c * CH + tt;
                size_t off = (size_t)t * (BSZ * IN_DIM) + obase;
                __nv_bfloat16 hi, lo;
                split_bf16(po, hi, lo);
                Ohi[off] = hi;
                Olo[off] = lo;
            }
        }
        __syncwarp();
        if (c + 2 < NC) issue(c + 2);
        else asm volatile("cp.async.commit_group;\n" ::);
    }
}

// ---------------- launcher ----------------
extern "C" void kernel_launch(void* const* d_in, const int* in_sizes, int n_in,
                              void* d_out, int out_size)
{
    const float* x      = (const float*)d_in[0];
    const float* ln_w   = (const float*)d_in[1];
    const float* ln_b   = (const float*)d_in[2];
    const float* w_slow = (const float*)d_in[3];
    const float* w_out  = (const float*)d_in[4];
    float* out = (float*)d_out;

    float *p_qkvb, *p_q, *p_k, *p_v, *p_beta;
    __nv_bfloat16 *p_h_hi, *p_h_lo, *p_o_hi, *p_o_lo;
    __nv_bfloat16 *p_ws_hi, *p_ws_lo, *p_wo_hi, *p_wo_lo;
    cudaGetSymbolAddress((void**)&p_qkvb, g_qkvb);
    cudaGetSymbolAddress((void**)&p_q,    g_q);
    cudaGetSymbolAddress((void**)&p_k,    g_k);
    cudaGetSymbolAddress((void**)&p_v,    g_v);
    cudaGetSymbolAddress((void**)&p_beta, g_beta);
    cudaGetSymbolAddress((void**)&p_h_hi, g_h_hi);
    cudaGetSymbolAddress((void**)&p_h_lo, g_h_lo);
    cudaGetSymbolAddress((void**)&p_o_hi, g_o_hi);
    cudaGetSymbolAddress((void**)&p_o_lo, g_o_lo);
    cudaGetSymbolAddress((void**)&p_ws_hi, g_ws_t_hi);
    cudaGetSymbolAddress((void**)&p_ws_lo, g_ws_t_lo);
    cudaGetSymbolAddress((void**)&p_wo_hi, g_wo_t_hi);
    cudaGetSymbolAddress((void**)&p_wo_lo, g_wo_t_lo);

    cudaFuncSetAttribute(gemm_bf16x3, cudaFuncAttributeMaxDynamicSharedMemorySize,
                         GEMM_SMEM_BYTES);

    // 0. split+transpose weights (zero-padded to NOUT_PAD rows)
    {
        dim3 blk(32, 8);
        dim3 g1(NOUT_PAD / 32, IN_DIM / 32);
        split_transpose<<<g1, blk>>>(w_slow, p_ws_hi, p_ws_lo, IN_DIM, NOUT);
        dim3 g2(IN_DIM / 32, IN_DIM / 32);
        split_transpose<<<g2, blk>>>(w_out, p_wo_hi, p_wo_lo, IN_DIM, IN_DIM);
    }

    // 1. LayerNorm -> split bf16
    ln_kernel<<<NROWS, 256>>>(x, ln_w, ln_b, p_h_hi, p_h_lo);

    // 2. qkvb = h @ w_slow   (bf16x3, ldmatrix, 3-stage)
    {
        dim3 grid(NOUT_PAD / 128, NROWS / 128);   // 25 x 128
        gemm_bf16x3<<<grid, 256, GEMM_SMEM_BYTES>>>(p_h_hi, p_h_lo, p_ws_hi, p_ws_lo,
                                                    nullptr, p_qkvb, NOUT, IN_DIM);
    }

    // 3. transform -> q,k,v,beta in [bh][t][d] layout
    transform_kernel<<<(NROWS * NH) / 8, 256>>>(p_qkvb, p_q, p_k, p_v, p_beta);

    // 4. delta-rule scan
    scan_kernel<<<BSZ * NH * 8, 32>>>(p_q, p_k, p_v, p_beta, p_o_hi, p_o_lo);

    // 5. out = x + scan_out @ w_out   (bf16x3, ldmatrix, 3-stage)
    {
        dim3 grid(IN_DIM / 128, NROWS / 128);     // 8 x 128
        gemm_bf16x3<<<grid, 256, GEMM_SMEM_BYTES>>>(p_o_hi, p_o_lo, p_wo_hi, p_wo_lo,
                                                    x, out, IN_DIM, IN_DIM);
    }
}